// round 2
// baseline (speedup 1.0000x reference)
#include <cuda_runtime.h>

// RNN car-following model, GB300 sm_103a — round 2: f32x2-packed, 2 vehicles/warp.
// One warp = one vehicle PAIR; lo half of every 64-bit reg = vehicle A, hi = vehicle B.
// All heavy math uses fma.rn.f32x2 (FFMA2): 2 fp32 FMAs per issue slot.

#define PAST 25
#define WPB 4
#define THREADS (WPB * 32)

typedef unsigned long long u64;

__device__ __forceinline__ u64 pk(float lo, float hi) {
    u64 r; asm("mov.b64 %0, {%1, %2};" : "=l"(r) : "f"(lo), "f"(hi)); return r;
}
__device__ __forceinline__ void upk(u64 v, float& lo, float& hi) {
    asm("mov.b64 {%0, %1}, %2;" : "=f"(lo), "=f"(hi) : "l"(v));
}
__device__ __forceinline__ u64 f2fma(u64 a, u64 b, u64 c) {
    u64 d; asm("fma.rn.f32x2 %0, %1, %2, %3;" : "=l"(d) : "l"(a), "l"(b), "l"(c)); return d;
}
__device__ __forceinline__ u64 f2add(u64 a, u64 b) {
    u64 d; asm("add.rn.f32x2 %0, %1, %2;" : "=l"(d) : "l"(a), "l"(b)); return d;
}
__device__ __forceinline__ u64 f2mul(u64 a, u64 b) {
    u64 d; asm("mul.rn.f32x2 %0, %1, %2;" : "=l"(d) : "l"(a), "l"(b)); return d;
}

// ---- shared layout (bytes) ----
// w2d   u64[6144]  @0        (49152)  conv2 weights, each scalar duplicated {w,w}, [ci][k][co]
// d2ws  f32[4608]  @49152    (18432)  dense1 384x10, rows padded to 12
// w1s   f32[288]   @67584
// b1s   f32[32]    @68736
// b2s   f32[64]    @68864
// d2bs  f32[16]    @69120
// d1ws  f32[16]    @69184   (w[0..9], bias at [15])
// per-warp @69248, stride 8704 B:
//   xs     u64[96]    (3x32, channel-major)
//   pool1t u64[544]   (32 x 17; 13 used, pad 17)
//   pool2s u64[384]   (6 x 64, flatten order)
//   posb   u64[32]    circular
//   spdb   u64[32]    circular
#define OFF_W2D   0
#define OFF_D2W   49152
#define OFF_W1    67584
#define OFF_B1    68736
#define OFF_B2    68864
#define OFF_D2B   69120
#define OFF_D1W   69184
#define OFF_WARP  69248
#define WARP_BYTES 8704
#define SMEM_BYTES (OFF_WARP + WPB * WARP_BYTES)

__global__ __launch_bounds__(THREADS, 2)
void rnncf_kernel(const float* __restrict__ lead,   // [nveh][lead_len][2]
                  const float* __restrict__ curst,  // [nveh][25][2]
                  const float* __restrict__ w1,     // [3][3][32]
                  const float* __restrict__ b1,     // [32]
                  const float* __restrict__ w2,     // [3][32][64]
                  const float* __restrict__ b2,     // [64]
                  const float* __restrict__ d2w,    // [384][10]
                  const float* __restrict__ d2b,    // [10]
                  const float* __restrict__ d1w,    // [10][1]
                  const float* __restrict__ d1b,    // [1]
                  float* __restrict__ out,          // [nveh][nt][2]
                  int nveh, int nt, int lead_len)
{
    extern __shared__ __align__(16) unsigned char smraw[];
    u64*   w2d  = (u64*)  (smraw + OFF_W2D);
    float* d2ws = (float*)(smraw + OFF_D2W);
    float* w1s  = (float*)(smraw + OFF_W1);
    float* b1s  = (float*)(smraw + OFF_B1);
    float* b2s  = (float*)(smraw + OFF_B2);
    float* d2bs = (float*)(smraw + OFF_D2B);
    float* d1ws = (float*)(smraw + OFF_D1W);

    const int tid = threadIdx.x;

    // ---- stage weights ----
    for (int i = tid; i < 6144; i += THREADS) {
        int co = i & 63; int r = i >> 6; int ci = r / 3; int k = r - ci * 3;
        float w = w2[(k * 32 + ci) * 64 + co];      // -> [ci][k][co], duplicated
        w2d[i] = pk(w, w);
    }
    for (int i = tid; i < 384 * 12; i += THREADS) {
        int o = i % 12; int r = i / 12;
        d2ws[i] = (o < 10) ? d2w[r * 10 + o] : 0.0f;
    }
    for (int i = tid; i < 288; i += THREADS) w1s[i] = w1[i];
    for (int i = tid; i < 32;  i += THREADS) b1s[i] = b1[i];
    for (int i = tid; i < 64;  i += THREADS) b2s[i] = b2[i];
    if (tid < 10) d2bs[tid] = d2b[tid];
    if (tid < 10) d1ws[tid] = d1w[tid];
    if (tid == 0) d1ws[15] = d1b[0];
    __syncthreads();

    const int warp = tid >> 5;
    const int lane = tid & 31;
    const int pair = blockIdx.x * WPB + warp;
    const int vA = 2 * pair;
    if (vA >= nveh) return;
    const bool hasB = (vA + 1) < nveh;
    const int vB = hasB ? vA + 1 : vA;

    u64* warpbuf = (u64*)(smraw + OFF_WARP + warp * WARP_BYTES);
    u64* xs     = warpbuf;          // 96
    u64* pool1t = xs + 96;          // 544
    u64* pool2s = pool1t + 544;     // 384
    u64* posb   = pool2s + 384;     // 32
    u64* spdb   = posb + 32;        // 32

    const float2* leadA = (const float2*)(lead + (size_t)vA * lead_len * 2);
    const float2* leadB = (const float2*)(lead + (size_t)vB * lead_len * 2);

    if (lane < PAST) {
        float2 cA = ((const float2*)curst)[vA * PAST + lane];
        float2 cB = ((const float2*)curst)[vB * PAST + lane];
        posb[lane] = pk(cA.x, cB.x);
        spdb[lane] = pk(cA.y, cB.y);
    }

    // conv1 weights packed into registers: w1r[k*3+ci]
    u64 w1r[9];
#pragma unroll
    for (int q = 0; q < 9; q++) { float w = w1s[q * 32 + lane]; w1r[q] = pk(w, w); }
    const u64 b1p  = pk(b1s[lane], b1s[lane]);
    const float b2r0 = b2s[lane];
    const float b2r1 = b2s[lane + 32];
    const float d1bias = d1ws[15];

    const u64 C_NEG1 = pk(-1.0f, -1.0f);
    const u64 C_HD   = pk(1.0f / 200.0f, 1.0f / 200.0f);
    const u64 C_V    = pk(1.0f / 40.0f,  1.0f / 40.0f);

    int head = 0;
    __syncwarp();

    for (int t = 0; t < nt; t++) {
        // ---- A: build packed input window ----
        if (lane < PAST) {
            int s = t + lane;
            float2 lA = leadA[s];
            float2 lB = leadB[s];
            u64 lp = pk(lA.x, lB.x);
            u64 ls = pk(lA.y, lB.y);
            u64 pw = posb[(head + lane) & 31];
            u64 sw = spdb[(head + lane) & 31];
            xs[lane]      = f2mul(f2fma(pw, C_NEG1, lp), C_HD);  // (lp-pos)/200
            xs[32 + lane] = f2mul(sw, C_V);
            xs[64 + lane] = f2mul(ls, C_V);
        }
        __syncwarp();

        // ---- B: conv1 (SAME) + relu + maxpool2 -> pool1t[ci][13] ----
        {
            u64 xm0 = 0, xm1 = 0, xm2 = 0;                      // col w-1 (zeros pack = 0ull)
            u64 x00 = xs[0], x01 = xs[32], x02 = xs[64];        // col w
            float plo = 0.f, phi = 0.f;
#pragma unroll
            for (int w = 0; w < 25; w++) {
                u64 xp0, xp1, xp2;
                if (w < 24) { xp0 = xs[w + 1]; xp1 = xs[32 + w + 1]; xp2 = xs[64 + w + 1]; }
                else        { xp0 = 0; xp1 = 0; xp2 = 0; }
                u64 val = b1p;
                val = f2fma(xm0, w1r[0], val); val = f2fma(xm1, w1r[1], val); val = f2fma(xm2, w1r[2], val);
                val = f2fma(x00, w1r[3], val); val = f2fma(x01, w1r[4], val); val = f2fma(x02, w1r[5], val);
                val = f2fma(xp0, w1r[6], val); val = f2fma(xp1, w1r[7], val); val = f2fma(xp2, w1r[8], val);
                float vlo, vhi; upk(val, vlo, vhi);
                vlo = fmaxf(vlo, 0.0f); vhi = fmaxf(vhi, 0.0f);
                if ((w & 1) == 0) {
                    if (w == 24) pool1t[lane * 17 + 12] = pk(vlo, vhi);
                    else { plo = vlo; phi = vhi; }
                } else {
                    pool1t[lane * 17 + (w >> 1)] = pk(fmaxf(plo, vlo), fmaxf(phi, vhi));
                }
                xm0 = x00; xm1 = x01; xm2 = x02;
                x00 = xp0; x01 = xp1; x02 = xp2;
            }
        }
        __syncwarp();

        // ---- C: conv2 (VALID 32->64), lane handles co=lane and co=lane+32 ----
        u64 a0[11], a1[11];
#pragma unroll
        for (int q = 0; q < 11; q++) { a0[q] = 0; a1[q] = 0; }
#pragma unroll 4
        for (int ci = 0; ci < 32; ci++) {
            u64 p[13];
#pragma unroll
            for (int j = 0; j < 13; j++) p[j] = pool1t[ci * 17 + j];    // broadcast LDS.64
            u64 wa0 = w2d[(ci * 3 + 0) * 64 + lane];
            u64 wa1 = w2d[(ci * 3 + 1) * 64 + lane];
            u64 wa2 = w2d[(ci * 3 + 2) * 64 + lane];
            u64 wb0 = w2d[(ci * 3 + 0) * 64 + lane + 32];
            u64 wb1 = w2d[(ci * 3 + 1) * 64 + lane + 32];
            u64 wb2 = w2d[(ci * 3 + 2) * 64 + lane + 32];
#pragma unroll
            for (int q = 0; q < 11; q++) {
                a0[q] = f2fma(p[q],     wa0, a0[q]);
                a0[q] = f2fma(p[q + 1], wa1, a0[q]);
                a0[q] = f2fma(p[q + 2], wa2, a0[q]);
                a1[q] = f2fma(p[q],     wb0, a1[q]);
                a1[q] = f2fma(p[q + 1], wb1, a1[q]);
                a1[q] = f2fma(p[q + 2], wb2, a1[q]);
            }
        }
        // bias + relu + maxpool2 (pairs (0,1)..(8,9),(10,pad)) -> pool2s[6][64]
#pragma unroll
        for (int pp = 0; pp < 6; pp++) {
            float e0lo, e0hi, f0lo, f0hi;
            upk(a0[2 * pp], e0lo, e0hi);
            upk(a1[2 * pp], f0lo, f0hi);
            float r0lo = fmaxf(e0lo + b2r0, 0.0f), r0hi = fmaxf(e0hi + b2r0, 0.0f);
            float r1lo = fmaxf(f0lo + b2r1, 0.0f), r1hi = fmaxf(f0hi + b2r1, 0.0f);
            if (pp < 5) {
                float e1lo, e1hi, f1lo, f1hi;
                upk(a0[2 * pp + 1], e1lo, e1hi);
                upk(a1[2 * pp + 1], f1lo, f1hi);
                r0lo = fmaxf(r0lo, fmaxf(e1lo + b2r0, 0.0f));
                r0hi = fmaxf(r0hi, fmaxf(e1hi + b2r0, 0.0f));
                r1lo = fmaxf(r1lo, fmaxf(f1lo + b2r1, 0.0f));
                r1hi = fmaxf(r1hi, fmaxf(f1hi + b2r1, 0.0f));
            }
            pool2s[pp * 64 + lane]      = pk(r0lo, r0hi);
            pool2s[pp * 64 + lane + 32] = pk(r1lo, r1hi);
        }
        __syncwarp();

        // ---- D: dense 384->10 (packed lane-partials + butterfly), relu, 10->1 ----
        u64 h[10];
#pragma unroll
        for (int o = 0; o < 10; o++) h[o] = 0;
#pragma unroll
        for (int m = 0; m < 12; m++) {
            int i = m * 32 + lane;
            u64 xv = pool2s[i];
            const float4* wp = (const float4*)&d2ws[i * 12];
            float4 wA = wp[0];
            float4 wB = wp[1];
            float2 wC = *(const float2*)&d2ws[i * 12 + 8];
            h[0] = f2fma(xv, pk(wA.x, wA.x), h[0]); h[1] = f2fma(xv, pk(wA.y, wA.y), h[1]);
            h[2] = f2fma(xv, pk(wA.z, wA.z), h[2]); h[3] = f2fma(xv, pk(wA.w, wA.w), h[3]);
            h[4] = f2fma(xv, pk(wB.x, wB.x), h[4]); h[5] = f2fma(xv, pk(wB.y, wB.y), h[5]);
            h[6] = f2fma(xv, pk(wB.z, wB.z), h[6]); h[7] = f2fma(xv, pk(wB.w, wB.w), h[7]);
            h[8] = f2fma(xv, pk(wC.x, wC.x), h[8]); h[9] = f2fma(xv, pk(wC.y, wC.y), h[9]);
        }
#pragma unroll
        for (int off = 16; off > 0; off >>= 1) {
#pragma unroll
            for (int o = 0; o < 10; o++)
                h[o] = f2add(h[o], __shfl_xor_sync(0xffffffffu, h[o], off));
        }
        float s_lo = d1bias, s_hi = d1bias;
#pragma unroll
        for (int o = 0; o < 10; o++) {
            float hlo, hhi; upk(h[o], hlo, hhi);
            s_lo = fmaf(fmaxf(hlo + d2bs[o], 0.0f), d1ws[o], s_lo);
            s_hi = fmaf(fmaxf(hhi + d2bs[o], 0.0f), d1ws[o], s_hi);
        }
        float accA = 10.0f * s_lo - 6.0f;
        float accB = 10.0f * s_hi - 6.0f;

        // ---- E: state update + output ----
        if (lane == 0) {
            float pAlo, pBlo, sAlo, sBlo;
            upk(posb[(head + 24) & 31], pAlo, pBlo);
            upk(spdb[(head + 24) & 31], sAlo, sBlo);
            float npA = pAlo + 0.1f * sAlo;
            float nsA = sAlo + 0.1f * accA;
            float npB = pBlo + 0.1f * sBlo;
            float nsB = sBlo + 0.1f * accB;
            ((float2*)out)[(size_t)vA * nt + t] = make_float2(npA, nsA);
            if (hasB)
                ((float2*)out)[(size_t)vB * nt + t] = make_float2(npB, nsB);
            posb[(head + 25) & 31] = pk(npA, npB);
            spdb[(head + 25) & 31] = pk(nsA, nsB);
        }
        head = (head + 1) & 31;
        __syncwarp();
    }
}

extern "C" void kernel_launch(void* const* d_in, const int* in_sizes, int n_in,
                              void* d_out, int out_size) {
    const float* lead = (const float*)d_in[0];
    const float* curs = (const float*)d_in[1];
    // d_in[2] = mask : unused by the reference
    const float* w1  = (const float*)d_in[3];
    const float* b1  = (const float*)d_in[4];
    const float* w2  = (const float*)d_in[5];
    const float* b2  = (const float*)d_in[6];
    const float* d2w = (const float*)d_in[7];
    const float* d2b = (const float*)d_in[8];
    const float* d1w = (const float*)d_in[9];
    const float* d1b = (const float*)d_in[10];

    int nveh = in_sizes[1] / (2 * PAST);
    int lead_len = in_sizes[0] / (nveh * 2);
    int nt = out_size / (nveh * 2);

    cudaFuncSetAttribute(rnncf_kernel, cudaFuncAttributeMaxDynamicSharedMemorySize, SMEM_BYTES);

    int pairs = (nveh + 1) / 2;
    int blocks = (pairs + WPB - 1) / WPB;
    rnncf_kernel<<<blocks, THREADS, SMEM_BYTES>>>(
        lead, curs, w1, b1, w2, b2, d2w, d2b, d1w, d1b,
        (float*)d_out, nveh, nt, lead_len);
}

// round 3
// speedup vs baseline: 1.1910x; 1.1910x over previous
#include <cuda_runtime.h>

// RNN car-following model, GB300 sm_103a — round 3.
// FFMA2 (2 vehicles/warp) + occupancy fix: scalar conv2 weights (pack at use),
// pool2 kept in registers, pool1 rows 14-u64 padded for LDS.128 broadcast reads,
// WPB=5 / 67KB smem -> 3 CTAs/SM, single wave.

#define PAST 25
#define WPB 5
#define THREADS (WPB * 32)

typedef unsigned long long u64;

__device__ __forceinline__ u64 pk(float lo, float hi) {
    u64 r; asm("mov.b64 %0, {%1, %2};" : "=l"(r) : "f"(lo), "f"(hi)); return r;
}
__device__ __forceinline__ void upk(u64 v, float& lo, float& hi) {
    asm("mov.b64 {%0, %1}, %2;" : "=f"(lo), "=f"(hi) : "l"(v));
}
__device__ __forceinline__ u64 f2fma(u64 a, u64 b, u64 c) {
    u64 d; asm("fma.rn.f32x2 %0, %1, %2, %3;" : "=l"(d) : "l"(a), "l"(b), "l"(c)); return d;
}
__device__ __forceinline__ u64 f2add(u64 a, u64 b) {
    u64 d; asm("add.rn.f32x2 %0, %1, %2;" : "=l"(d) : "l"(a), "l"(b)); return d;
}
__device__ __forceinline__ u64 f2mul(u64 a, u64 b) {
    u64 d; asm("mul.rn.f32x2 %0, %1, %2;" : "=l"(d) : "l"(a), "l"(b)); return d;
}

// ---- shared layout (bytes) ----
// w2s  f32[6144] @0       (24576)  conv2 weights scalar, [ci][k][co]
// d2ws f32[4608] @24576   (18432)  dense 384x10, rows padded to 12
// w1s  f32[288]  @43008   (1152)
// b1s  f32[32]   @44160
// b2s  f32[64]   @44288
// d2bs f32[16]   @44544
// d1ws f32[16]   @44608   (w[0..9], bias at [15])
// per-warp @44672, stride 4864 B:
//   xs     u64[96]      (3x32, channel-major; slots 25..31 zeroed)
//   pool1t u64[448]     (32 rows x 14; 13 used, pad 14 -> 16B-aligned rows)
//   posb   u64[32], spdb u64[32]  circular
#define OFF_W2S   0
#define OFF_D2W   24576
#define OFF_W1    43008
#define OFF_B1    44160
#define OFF_B2    44288
#define OFF_D2B   44544
#define OFF_D1W   44608
#define OFF_WARP  44672
#define WARP_BYTES 4864
#define SMEM_BYTES (OFF_WARP + WPB * WARP_BYTES)

__global__ __launch_bounds__(THREADS, 3)
void rnncf_kernel(const float* __restrict__ lead,   // [nveh][lead_len][2]
                  const float* __restrict__ curst,  // [nveh][25][2]
                  const float* __restrict__ w1,     // [3][3][32]
                  const float* __restrict__ b1,     // [32]
                  const float* __restrict__ w2,     // [3][32][64]
                  const float* __restrict__ b2,     // [64]
                  const float* __restrict__ d2w,    // [384][10]
                  const float* __restrict__ d2b,    // [10]
                  const float* __restrict__ d1w,    // [10][1]
                  const float* __restrict__ d1b,    // [1]
                  float* __restrict__ out,          // [nveh][nt][2]
                  int nveh, int nt, int lead_len)
{
    extern __shared__ __align__(16) unsigned char smraw[];
    float* w2s  = (float*)(smraw + OFF_W2S);
    float* d2ws = (float*)(smraw + OFF_D2W);
    float* w1s  = (float*)(smraw + OFF_W1);
    float* b1s  = (float*)(smraw + OFF_B1);
    float* b2s  = (float*)(smraw + OFF_B2);
    float* d2bs = (float*)(smraw + OFF_D2B);
    float* d1ws = (float*)(smraw + OFF_D1W);

    const int tid = threadIdx.x;

    // ---- stage weights ----
    for (int i = tid; i < 6144; i += THREADS) {
        int co = i & 63; int r = i >> 6; int ci = r / 3; int k = r - ci * 3;
        w2s[i] = w2[(k * 32 + ci) * 64 + co];       // -> [ci][k][co]
    }
    for (int i = tid; i < 384 * 12; i += THREADS) {
        int o = i % 12; int r = i / 12;
        d2ws[i] = (o < 10) ? d2w[r * 10 + o] : 0.0f;
    }
    for (int i = tid; i < 288; i += THREADS) w1s[i] = w1[i];
    for (int i = tid; i < 32;  i += THREADS) b1s[i] = b1[i];
    for (int i = tid; i < 64;  i += THREADS) b2s[i] = b2[i];
    if (tid < 10) d2bs[tid] = d2b[tid];
    if (tid < 10) d1ws[tid] = d1w[tid];
    if (tid == 0) d1ws[15] = d1b[0];
    __syncthreads();

    const int warp = tid >> 5;
    const int lane = tid & 31;
    const int npairs = (nveh + 1) >> 1;
    const int pair = blockIdx.x * WPB + warp;
    if (pair >= npairs) return;
    const int vA = 2 * pair;
    const bool hasB = (vA + 1) < nveh;
    const int vB = hasB ? vA + 1 : vA;

    u64* warpbuf = (u64*)(smraw + OFF_WARP + warp * WARP_BYTES);
    u64* xs     = warpbuf;          // 96
    u64* pool1t = xs + 96;          // 448 (32 x 14)
    u64* posb   = pool1t + 448;     // 32
    u64* spdb   = posb + 32;        // 32

    const float2* leadA = (const float2*)(lead + (size_t)vA * lead_len * 2);
    const float2* leadB = (const float2*)(lead + (size_t)vB * lead_len * 2);

    if (lane < PAST) {
        float2 cA = ((const float2*)curst)[vA * PAST + lane];
        float2 cB = ((const float2*)curst)[vB * PAST + lane];
        posb[lane] = pk(cA.x, cB.x);
        spdb[lane] = pk(cA.y, cB.y);
    } else {
        xs[lane] = 0; xs[32 + lane] = 0; xs[64 + lane] = 0;   // permanent zero pad
    }

    // conv1 weights packed into registers: w1r[k*3+ci]
    u64 w1r[9];
#pragma unroll
    for (int q = 0; q < 9; q++) { float w = w1s[q * 32 + lane]; w1r[q] = pk(w, w); }
    const u64 b1p  = pk(b1s[lane], b1s[lane]);
    const float b2r0 = b2s[lane];
    const float b2r1 = b2s[lane + 32];
    const float d1bias = d1ws[15];

    const u64 C_NEG1 = pk(-1.0f, -1.0f);
    const u64 C_HD   = pk(1.0f / 200.0f, 1.0f / 200.0f);
    const u64 C_V    = pk(1.0f / 40.0f,  1.0f / 40.0f);

    int head = 0;
    __syncwarp();

    for (int t = 0; t < nt; t++) {
        // ---- A: packed input window ----
        if (lane < PAST) {
            int s = t + lane;
            float2 lA = leadA[s];
            float2 lB = leadB[s];
            u64 lp = pk(lA.x, lB.x);
            u64 ls = pk(lA.y, lB.y);
            u64 pw = posb[(head + lane) & 31];
            u64 sw = spdb[(head + lane) & 31];
            xs[lane]      = f2mul(f2fma(pw, C_NEG1, lp), C_HD);  // (lp-pos)/200
            xs[32 + lane] = f2mul(sw, C_V);
            xs[64 + lane] = f2mul(ls, C_V);
        }
        __syncwarp();

        // ---- B: conv1 (SAME) + relu + maxpool2 -> pool1t[ci][0..12] ----
        {
            u64 xm0 = 0, xm1 = 0, xm2 = 0;
            u64 x00 = xs[0], x01 = xs[32], x02 = xs[64];
            float plo = 0.f, phi = 0.f;
#pragma unroll
            for (int w = 0; w < 25; w++) {
                u64 xp0 = xs[w + 1], xp1 = xs[32 + w + 1], xp2 = xs[64 + w + 1]; // w=24 reads zero pad
                u64 val = b1p;
                val = f2fma(xm0, w1r[0], val); val = f2fma(xm1, w1r[1], val); val = f2fma(xm2, w1r[2], val);
                val = f2fma(x00, w1r[3], val); val = f2fma(x01, w1r[4], val); val = f2fma(x02, w1r[5], val);
                val = f2fma(xp0, w1r[6], val); val = f2fma(xp1, w1r[7], val); val = f2fma(xp2, w1r[8], val);
                float vlo, vhi; upk(val, vlo, vhi);
                vlo = fmaxf(vlo, 0.0f); vhi = fmaxf(vhi, 0.0f);
                if ((w & 1) == 0) {
                    if (w == 24) pool1t[lane * 14 + 12] = pk(vlo, vhi);
                    else { plo = vlo; phi = vhi; }
                } else {
                    pool1t[lane * 14 + (w >> 1)] = pk(fmaxf(plo, vlo), fmaxf(phi, vhi));
                }
                xm0 = x00; xm1 = x01; xm2 = x02;
                x00 = xp0; x01 = xp1; x02 = xp2;
            }
        }
        __syncwarp();

        // ---- C: conv2 (VALID 32->64); lane handles co=lane, co=lane+32 ----
        u64 a0[11], a1[11];
#pragma unroll
        for (int q = 0; q < 11; q++) { a0[q] = 0; a1[q] = 0; }
#pragma unroll 4
        for (int ci = 0; ci < 32; ci++) {
            // p[0..12] via LDS.128 broadcast pairs (+ final LDS.64)
            const ulonglong2* prow = (const ulonglong2*)(pool1t + ci * 14);
            u64 p[13];
#pragma unroll
            for (int h2 = 0; h2 < 6; h2++) {
                ulonglong2 q2 = prow[h2];
                p[2 * h2] = q2.x; p[2 * h2 + 1] = q2.y;
            }
            p[12] = pool1t[ci * 14 + 12];
            const float* wrow = &w2s[ci * 192];
            float s0 = wrow[lane],           s1 = wrow[64 + lane],       s2 = wrow[128 + lane];
            float s3 = wrow[lane + 32],      s4 = wrow[64 + lane + 32],  s5 = wrow[128 + lane + 32];
            u64 wa0 = pk(s0, s0), wa1 = pk(s1, s1), wa2 = pk(s2, s2);
            u64 wb0 = pk(s3, s3), wb1 = pk(s4, s4), wb2 = pk(s5, s5);
#pragma unroll
            for (int q = 0; q < 11; q++) {
                a0[q] = f2fma(p[q],     wa0, a0[q]);
                a0[q] = f2fma(p[q + 1], wa1, a0[q]);
                a0[q] = f2fma(p[q + 2], wa2, a0[q]);
                a1[q] = f2fma(p[q],     wb0, a1[q]);
                a1[q] = f2fma(p[q + 1], wb1, a1[q]);
                a1[q] = f2fma(p[q + 2], wb2, a1[q]);
            }
        }
        // bias + relu + maxpool2 -> registers (flatten i = pp*64 + {0,32} + lane)
        u64 pl[6], ph[6];
#pragma unroll
        for (int pp = 0; pp < 6; pp++) {
            float e0lo, e0hi, f0lo, f0hi;
            upk(a0[2 * pp], e0lo, e0hi);
            upk(a1[2 * pp], f0lo, f0hi);
            float r0lo = fmaxf(e0lo + b2r0, 0.0f), r0hi = fmaxf(e0hi + b2r0, 0.0f);
            float r1lo = fmaxf(f0lo + b2r1, 0.0f), r1hi = fmaxf(f0hi + b2r1, 0.0f);
            if (pp < 5) {
                float e1lo, e1hi, f1lo, f1hi;
                upk(a0[2 * pp + 1], e1lo, e1hi);
                upk(a1[2 * pp + 1], f1lo, f1hi);
                r0lo = fmaxf(r0lo, fmaxf(e1lo + b2r0, 0.0f));
                r0hi = fmaxf(r0hi, fmaxf(e1hi + b2r0, 0.0f));
                r1lo = fmaxf(r1lo, fmaxf(f1lo + b2r1, 0.0f));
                r1hi = fmaxf(r1hi, fmaxf(f1hi + b2r1, 0.0f));
            }
            pl[pp] = pk(r0lo, r0hi);   // i = pp*64 + lane       (m = 2pp)
            ph[pp] = pk(r1lo, r1hi);   // i = pp*64 + 32 + lane  (m = 2pp+1)
        }

        // ---- D: dense 384->10 (packed lane-partials + butterfly), relu, 10->1 ----
        u64 h[10];
#pragma unroll
        for (int o = 0; o < 10; o++) h[o] = 0;
#pragma unroll
        for (int pp = 0; pp < 6; pp++) {
#pragma unroll
            for (int half = 0; half < 2; half++) {
                int m = 2 * pp + half;
                u64 xv = half ? ph[pp] : pl[pp];
                int i = m * 32 + lane;
                const float4* wp = (const float4*)&d2ws[i * 12];
                float4 wA = wp[0];
                float4 wB = wp[1];
                float2 wC = *(const float2*)&d2ws[i * 12 + 8];
                h[0] = f2fma(xv, pk(wA.x, wA.x), h[0]); h[1] = f2fma(xv, pk(wA.y, wA.y), h[1]);
                h[2] = f2fma(xv, pk(wA.z, wA.z), h[2]); h[3] = f2fma(xv, pk(wA.w, wA.w), h[3]);
                h[4] = f2fma(xv, pk(wB.x, wB.x), h[4]); h[5] = f2fma(xv, pk(wB.y, wB.y), h[5]);
                h[6] = f2fma(xv, pk(wB.z, wB.z), h[6]); h[7] = f2fma(xv, pk(wB.w, wB.w), h[7]);
                h[8] = f2fma(xv, pk(wC.x, wC.x), h[8]); h[9] = f2fma(xv, pk(wC.y, wC.y), h[9]);
            }
        }
#pragma unroll
        for (int off = 16; off > 0; off >>= 1) {
#pragma unroll
            for (int o = 0; o < 10; o++)
                h[o] = f2add(h[o], __shfl_xor_sync(0xffffffffu, h[o], off));
        }
        float s_lo = d1bias, s_hi = d1bias;
#pragma unroll
        for (int o = 0; o < 10; o++) {
            float hlo, hhi; upk(h[o], hlo, hhi);
            s_lo = fmaf(fmaxf(hlo + d2bs[o], 0.0f), d1ws[o], s_lo);
            s_hi = fmaf(fmaxf(hhi + d2bs[o], 0.0f), d1ws[o], s_hi);
        }
        float accA = 10.0f * s_lo - 6.0f;
        float accB = 10.0f * s_hi - 6.0f;

        // ---- E: state update + output ----
        if (lane == 0) {
            float pAlo, pBlo, sAlo, sBlo;
            upk(posb[(head + 24) & 31], pAlo, pBlo);
            upk(spdb[(head + 24) & 31], sAlo, sBlo);
            float npA = pAlo + 0.1f * sAlo;
            float nsA = sAlo + 0.1f * accA;
            float npB = pBlo + 0.1f * sBlo;
            float nsB = sBlo + 0.1f * accB;
            ((float2*)out)[(size_t)vA * nt + t] = make_float2(npA, nsA);
            if (hasB)
                ((float2*)out)[(size_t)vB * nt + t] = make_float2(npB, nsB);
            posb[(head + 25) & 31] = pk(npA, npB);
            spdb[(head + 25) & 31] = pk(nsA, nsB);
        }
        head = (head + 1) & 31;
        __syncwarp();
    }
}

extern "C" void kernel_launch(void* const* d_in, const int* in_sizes, int n_in,
                              void* d_out, int out_size) {
    const float* lead = (const float*)d_in[0];
    const float* curs = (const float*)d_in[1];
    // d_in[2] = mask : unused by the reference
    const float* w1  = (const float*)d_in[3];
    const float* b1  = (const float*)d_in[4];
    const float* w2  = (const float*)d_in[5];
    const float* b2  = (const float*)d_in[6];
    const float* d2w = (const float*)d_in[7];
    const float* d2b = (const float*)d_in[8];
    const float* d1w = (const float*)d_in[9];
    const float* d1b = (const float*)d_in[10];

    int nveh = in_sizes[1] / (2 * PAST);
    int lead_len = in_sizes[0] / (nveh * 2);
    int nt = out_size / (nveh * 2);

    cudaFuncSetAttribute(rnncf_kernel, cudaFuncAttributeMaxDynamicSharedMemorySize, SMEM_BYTES);

    int pairs = (nveh + 1) / 2;
    int blocks = (pairs + WPB - 1) / WPB;
    rnncf_kernel<<<blocks, THREADS, SMEM_BYTES>>>(
        lead, curs, w1, b1, w2, b2, d2w, d2b, d1w, d1b,
        (float*)d_out, nveh, nt, lead_len);
}

// round 4
// speedup vs baseline: 2.3861x; 2.0034x over previous
#include <cuda_runtime.h>

// RNN car-following model, GB300 sm_103a — round 4.
// Incremental conv2 via the period-2 shift identity:
//   conv2_{t+2}[q] == conv2_t[q+1]  (bit-exact)  for q in [1..8];
// only q in {0,9,10} are recomputed each step. History kept in two 8-deep
// register delay lines (even/odd step parity), seeded by full passes at t=0,1.
// Layouts tuned for smem-crossbar (wavefront) minimization:
//   pool1 transposed [j][ci] (stride-1 STS), dense weights duplicated-u64 [o][i].

#define PAST 25
#define WPB 14
#define THREADS (WPB * 32)

typedef unsigned long long u64;

__device__ __forceinline__ u64 pk(float lo, float hi) {
    u64 r; asm("mov.b64 %0, {%1, %2};" : "=l"(r) : "f"(lo), "f"(hi)); return r;
}
__device__ __forceinline__ void upk(u64 v, float& lo, float& hi) {
    asm("mov.b64 {%0, %1}, %2;" : "=f"(lo), "=f"(hi) : "l"(v));
}
__device__ __forceinline__ u64 f2fma(u64 a, u64 b, u64 c) {
    u64 d; asm("fma.rn.f32x2 %0, %1, %2, %3;" : "=l"(d) : "l"(a), "l"(b), "l"(c)); return d;
}
__device__ __forceinline__ u64 f2add(u64 a, u64 b) {
    u64 d; asm("add.rn.f32x2 %0, %1, %2;" : "=l"(d) : "l"(a), "l"(b)); return d;
}
__device__ __forceinline__ u64 f2mul(u64 a, u64 b) {
    u64 d; asm("mul.rn.f32x2 %0, %1, %2;" : "=l"(d) : "l"(a), "l"(b)); return d;
}

// ---- shared layout (bytes) ----
// w2s   f32[6144] @0      (24576)  conv2 weights scalar, [ci][k][co]
// d2wd  u64[3840] @24576  (30720)  dense 384x10 duplicated {w,w}, layout [o][i]
// w1s   f32[288]  @55296
// b1s   f32[32]   @56448
// b2s   f32[64]   @56576
// d2bs  f32[16]   @56832
// d1ws  f32[16]   @56896  (w[0..9], bias at [15])
// per-warp @56960, stride 4608 B:
//   xs     u64[96]   (3x32, channel-major; slots 25..31 zeroed once)
//   pool1T u64[416]  ([j][ci] : 13 x 32, stride-1 in ci -> conflict-free)
//   posb   u64[32], spdb u64[32]  circular
#define OFF_W2S   0
#define OFF_D2WD  24576
#define OFF_W1    55296
#define OFF_B1    56448
#define OFF_B2    56576
#define OFF_D2B   56832
#define OFF_D1W   56896
#define OFF_WARP  56960
#define WARP_BYTES 4608
#define SMEM_BYTES (OFF_WARP + WPB * WARP_BYTES)

__global__ __launch_bounds__(THREADS, 1)
void rnncf_kernel(const float* __restrict__ lead,   // [nveh][lead_len][2]
                  const float* __restrict__ curst,  // [nveh][25][2]
                  const float* __restrict__ w1,     // [3][3][32]
                  const float* __restrict__ b1,     // [32]
                  const float* __restrict__ w2,     // [3][32][64]
                  const float* __restrict__ b2,     // [64]
                  const float* __restrict__ d2w,    // [384][10]
                  const float* __restrict__ d2b,    // [10]
                  const float* __restrict__ d1w,    // [10][1]
                  const float* __restrict__ d1b,    // [1]
                  float* __restrict__ out,          // [nveh][nt][2]
                  int nveh, int nt, int lead_len)
{
    extern __shared__ __align__(16) unsigned char smraw[];
    float* w2s  = (float*)(smraw + OFF_W2S);
    u64*   d2wd = (u64*)  (smraw + OFF_D2WD);
    float* w1s  = (float*)(smraw + OFF_W1);
    float* b1s  = (float*)(smraw + OFF_B1);
    float* b2s  = (float*)(smraw + OFF_B2);
    float* d2bs = (float*)(smraw + OFF_D2B);
    float* d1ws = (float*)(smraw + OFF_D1W);

    const int tid = threadIdx.x;

    // ---- stage weights ----
    for (int i = tid; i < 6144; i += THREADS) {
        int co = i & 63; int r = i >> 6; int ci = r / 3; int k = r - ci * 3;
        w2s[i] = w2[(k * 32 + ci) * 64 + co];       // -> [ci][k][co]
    }
    for (int i = tid; i < 3840; i += THREADS) {
        int o = i / 384; int r = i - o * 384;       // [o][i]
        float w = d2w[r * 10 + o];
        d2wd[i] = pk(w, w);
    }
    for (int i = tid; i < 288; i += THREADS) w1s[i] = w1[i];
    for (int i = tid; i < 32;  i += THREADS) b1s[i] = b1[i];
    for (int i = tid; i < 64;  i += THREADS) b2s[i] = b2[i];
    if (tid < 10) d2bs[tid] = d2b[tid];
    if (tid < 10) d1ws[tid] = d1w[tid];
    if (tid == 0) d1ws[15] = d1b[0];
    __syncthreads();

    const int warp = tid >> 5;
    const int lane = tid & 31;
    const int npairs = (nveh + 1) >> 1;
    const int pair = blockIdx.x * WPB + warp;
    if (pair >= npairs) return;
    const int vA = 2 * pair;
    const bool hasB = (vA + 1) < nveh;
    const int vB = hasB ? vA + 1 : vA;

    u64* warpbuf = (u64*)(smraw + OFF_WARP + warp * WARP_BYTES);
    u64* xs     = warpbuf;          // 96
    u64* pool1T = xs + 96;          // 416  ([j][ci])
    u64* posb   = pool1T + 416;     // 32
    u64* spdb   = posb + 32;        // 32

    const float2* leadA = (const float2*)(lead + (size_t)vA * lead_len * 2);
    const float2* leadB = (const float2*)(lead + (size_t)vB * lead_len * 2);

    if (lane < PAST) {
        float2 cA = ((const float2*)curst)[vA * PAST + lane];
        float2 cB = ((const float2*)curst)[vB * PAST + lane];
        posb[lane] = pk(cA.x, cB.x);
        spdb[lane] = pk(cA.y, cB.y);
    } else {
        xs[lane] = 0; xs[32 + lane] = 0; xs[64 + lane] = 0;   // permanent zero pad
    }

    const u64 b1p  = pk(b1s[lane], b1s[lane]);
    const float b2r0 = b2s[lane];
    const float b2r1 = b2s[lane + 32];
    const float d1bias = d1ws[15];

    const u64 C_NEG1 = pk(-1.0f, -1.0f);
    const u64 C_HD   = pk(1.0f / 200.0f, 1.0f / 200.0f);
    const u64 C_V    = pk(1.0f / 40.0f,  1.0f / 40.0f);

    int head = 0;
    __syncwarp();

    // conv1 weights packed: w1r[k*3+ci]
    u64 w1r[9];
#pragma unroll
    for (int q = 0; q < 9; q++) { float w = w1s[q * 32 + lane]; w1r[q] = pk(w, w); }

    // delay lines: l0/l1 hold conv2_{t-2}[2..9] for this step's parity (co=lane / co=lane+32)
    u64 lnE0[8], lnE1[8], lnO0[8], lnO1[8];

    auto conv1_at = [&](u64 xm0, u64 xm1, u64 xm2, u64 x00, u64 x01, u64 x02,
                        u64 xp0, u64 xp1, u64 xp2, float& vlo, float& vhi) {
        u64 val = b1p;
        val = f2fma(xm0, w1r[0], val); val = f2fma(xm1, w1r[1], val); val = f2fma(xm2, w1r[2], val);
        val = f2fma(x00, w1r[3], val); val = f2fma(x01, w1r[4], val); val = f2fma(x02, w1r[5], val);
        val = f2fma(xp0, w1r[6], val); val = f2fma(xp1, w1r[7], val); val = f2fma(xp2, w1r[8], val);
        upk(val, vlo, vhi);
        vlo = fmaxf(vlo, 0.0f); vhi = fmaxf(vhi, 0.0f);
    };

    auto stepf = [&](int t, u64 (&l0)[8], u64 (&l1)[8]) {
        // ---- A: packed input window ----
        if (lane < PAST) {
            int s = t + lane;
            float2 lA = leadA[s];
            float2 lB = leadB[s];
            u64 lp = pk(lA.x, lB.x);
            u64 ls = pk(lA.y, lB.y);
            u64 pw = posb[(head + lane) & 31];
            u64 sw = spdb[(head + lane) & 31];
            xs[lane]      = f2mul(f2fma(pw, C_NEG1, lp), C_HD);
            xs[32 + lane] = f2mul(sw, C_V);
            xs[64 + lane] = f2mul(ls, C_V);
        }
        __syncwarp();

        u64 c0[11], c1[11];   // this step's conv2 pre-bias outputs (co=lane / co=lane+32)

        if (t >= 2) {
            // ---- conv1 partial: only pool1 j in {0,1,2} and {8..12} ----
            {   // range w=0..5 -> j=0,1,2
                u64 xm0 = 0, xm1 = 0, xm2 = 0;
                u64 x00 = xs[0], x01 = xs[32], x02 = xs[64];
                float plo = 0.f, phi = 0.f;
#pragma unroll
                for (int w = 0; w < 6; w++) {
                    u64 xp0 = xs[w + 1], xp1 = xs[33 + w], xp2 = xs[65 + w];
                    float vlo, vhi;
                    conv1_at(xm0, xm1, xm2, x00, x01, x02, xp0, xp1, xp2, vlo, vhi);
                    if ((w & 1) == 0) { plo = vlo; phi = vhi; }
                    else pool1T[(w >> 1) * 32 + lane] = pk(fmaxf(plo, vlo), fmaxf(phi, vhi));
                    xm0 = x00; xm1 = x01; xm2 = x02;
                    x00 = xp0; x01 = xp1; x02 = xp2;
                }
            }
            {   // range w=16..24 -> j=8..12
                u64 xm0 = xs[15], xm1 = xs[47], xm2 = xs[79];
                u64 x00 = xs[16], x01 = xs[48], x02 = xs[80];
                float plo = 0.f, phi = 0.f;
#pragma unroll
                for (int w = 16; w < 25; w++) {
                    u64 xp0 = xs[w + 1], xp1 = xs[33 + w], xp2 = xs[65 + w];  // w=24 reads zero pad
                    float vlo, vhi;
                    conv1_at(xm0, xm1, xm2, x00, x01, x02, xp0, xp1, xp2, vlo, vhi);
                    if ((w & 1) == 0) {
                        if (w == 24) pool1T[12 * 32 + lane] = pk(vlo, vhi);
                        else { plo = vlo; phi = vhi; }
                    } else {
                        pool1T[(w >> 1) * 32 + lane] = pk(fmaxf(plo, vlo), fmaxf(phi, vhi));
                    }
                    xm0 = x00; xm1 = x01; xm2 = x02;
                    x00 = xp0; x01 = xp1; x02 = xp2;
                }
            }
            __syncwarp();

            // ---- conv2 incremental: recompute q = 0, 9, 10 only ----
            u64 n0a = 0, n9a = 0, n10a = 0, n0b = 0, n9b = 0, n10b = 0;
#pragma unroll 4
            for (int ci = 0; ci < 32; ci++) {
                u64 p0  = pool1T[ci],            p1  = pool1T[32 + ci],  p2  = pool1T[64 + ci];
                u64 p9  = pool1T[288 + ci],      p10 = pool1T[320 + ci];
                u64 p11 = pool1T[352 + ci],      p12 = pool1T[384 + ci];
                const float* wrow = &w2s[ci * 192];
                float s0 = wrow[lane],      s1 = wrow[64 + lane],  s2 = wrow[128 + lane];
                float s3 = wrow[32 + lane], s4 = wrow[96 + lane],  s5 = wrow[160 + lane];
                u64 wa0 = pk(s0, s0), wa1 = pk(s1, s1), wa2 = pk(s2, s2);
                u64 wb0 = pk(s3, s3), wb1 = pk(s4, s4), wb2 = pk(s5, s5);
                n0a  = f2fma(p0,  wa0, n0a);  n0a  = f2fma(p1,  wa1, n0a);  n0a  = f2fma(p2,  wa2, n0a);
                n9a  = f2fma(p9,  wa0, n9a);  n9a  = f2fma(p10, wa1, n9a);  n9a  = f2fma(p11, wa2, n9a);
                n10a = f2fma(p10, wa0, n10a); n10a = f2fma(p11, wa1, n10a); n10a = f2fma(p12, wa2, n10a);
                n0b  = f2fma(p0,  wb0, n0b);  n0b  = f2fma(p1,  wb1, n0b);  n0b  = f2fma(p2,  wb2, n0b);
                n9b  = f2fma(p9,  wb0, n9b);  n9b  = f2fma(p10, wb1, n9b);  n9b  = f2fma(p11, wb2, n9b);
                n10b = f2fma(p10, wb0, n10b); n10b = f2fma(p11, wb1, n10b); n10b = f2fma(p12, wb2, n10b);
            }
            c0[0] = n0a; c1[0] = n0b;
#pragma unroll
            for (int q = 1; q <= 8; q++) { c0[q] = l0[q - 1]; c1[q] = l1[q - 1]; }
            c0[9] = n9a; c0[10] = n10a; c1[9] = n9b; c1[10] = n10b;
            // update delay line: now holds conv2_t[2..9]
#pragma unroll
            for (int j = 0; j < 7; j++) { l0[j] = l0[j + 1]; l1[j] = l1[j + 1]; }
            l0[7] = n9a; l1[7] = n9b;
        } else {
            // ---- FULL path (t = 0, 1): conv1 all positions ----
            {
                u64 xm0 = 0, xm1 = 0, xm2 = 0;
                u64 x00 = xs[0], x01 = xs[32], x02 = xs[64];
                float plo = 0.f, phi = 0.f;
#pragma unroll
                for (int w = 0; w < 25; w++) {
                    u64 xp0 = xs[w + 1], xp1 = xs[33 + w], xp2 = xs[65 + w];
                    float vlo, vhi;
                    conv1_at(xm0, xm1, xm2, x00, x01, x02, xp0, xp1, xp2, vlo, vhi);
                    if ((w & 1) == 0) {
                        if (w == 24) pool1T[12 * 32 + lane] = pk(vlo, vhi);
                        else { plo = vlo; phi = vhi; }
                    } else {
                        pool1T[(w >> 1) * 32 + lane] = pk(fmaxf(plo, vlo), fmaxf(phi, vhi));
                    }
                    xm0 = x00; xm1 = x01; xm2 = x02;
                    x00 = xp0; x01 = xp1; x02 = xp2;
                }
            }
            __syncwarp();
            // ---- full conv2 ----
            u64 a0[11], a1[11];
#pragma unroll
            for (int q = 0; q < 11; q++) { a0[q] = 0; a1[q] = 0; }
#pragma unroll 2
            for (int ci = 0; ci < 32; ci++) {
                u64 p[13];
#pragma unroll
                for (int j = 0; j < 13; j++) p[j] = pool1T[j * 32 + ci];
                const float* wrow = &w2s[ci * 192];
                float s0 = wrow[lane],      s1 = wrow[64 + lane],  s2 = wrow[128 + lane];
                float s3 = wrow[32 + lane], s4 = wrow[96 + lane],  s5 = wrow[160 + lane];
                u64 wa0 = pk(s0, s0), wa1 = pk(s1, s1), wa2 = pk(s2, s2);
                u64 wb0 = pk(s3, s3), wb1 = pk(s4, s4), wb2 = pk(s5, s5);
#pragma unroll
                for (int q = 0; q < 11; q++) {
                    a0[q] = f2fma(p[q], wa0, a0[q]);
                    a0[q] = f2fma(p[q + 1], wa1, a0[q]);
                    a0[q] = f2fma(p[q + 2], wa2, a0[q]);
                    a1[q] = f2fma(p[q], wb0, a1[q]);
                    a1[q] = f2fma(p[q + 1], wb1, a1[q]);
                    a1[q] = f2fma(p[q + 2], wb2, a1[q]);
                }
            }
#pragma unroll
            for (int q = 0; q < 11; q++) { c0[q] = a0[q]; c1[q] = a1[q]; }
#pragma unroll
            for (int j = 0; j < 8; j++) { l0[j] = a0[j + 2]; l1[j] = a1[j + 2]; }
        }

        // ---- pool2 (bias + relu + maxpool2) -> registers ----
        u64 pl[6], ph[6];
#pragma unroll
        for (int pp = 0; pp < 6; pp++) {
            float e0lo, e0hi, f0lo, f0hi;
            upk(c0[2 * pp], e0lo, e0hi);
            upk(c1[2 * pp], f0lo, f0hi);
            float r0lo = fmaxf(e0lo + b2r0, 0.0f), r0hi = fmaxf(e0hi + b2r0, 0.0f);
            float r1lo = fmaxf(f0lo + b2r1, 0.0f), r1hi = fmaxf(f0hi + b2r1, 0.0f);
            if (pp < 5) {
                float e1lo, e1hi, f1lo, f1hi;
                upk(c0[2 * pp + 1], e1lo, e1hi);
                upk(c1[2 * pp + 1], f1lo, f1hi);
                r0lo = fmaxf(r0lo, fmaxf(e1lo + b2r0, 0.0f));
                r0hi = fmaxf(r0hi, fmaxf(e1hi + b2r0, 0.0f));
                r1lo = fmaxf(r1lo, fmaxf(f1lo + b2r1, 0.0f));
                r1hi = fmaxf(r1hi, fmaxf(f1hi + b2r1, 0.0f));
            }
            pl[pp] = pk(r0lo, r0hi);   // i = pp*64 + lane
            ph[pp] = pk(r1lo, r1hi);   // i = pp*64 + 32 + lane
        }

        // ---- dense 384->10 (dup-u64 weights, conflict-free), butterfly, 10->1 ----
        u64 h[10];
#pragma unroll
        for (int o = 0; o < 10; o++) h[o] = 0;
#pragma unroll
        for (int pp = 0; pp < 6; pp++) {
#pragma unroll
            for (int half = 0; half < 2; half++) {
                u64 xv = half ? ph[pp] : pl[pp];
                int i = (2 * pp + half) * 32 + lane;
#pragma unroll
                for (int o = 0; o < 10; o++)
                    h[o] = f2fma(xv, d2wd[o * 384 + i], h[o]);
            }
        }
#pragma unroll
        for (int off = 16; off > 0; off >>= 1) {
#pragma unroll
            for (int o = 0; o < 10; o++)
                h[o] = f2add(h[o], __shfl_xor_sync(0xffffffffu, h[o], off));
        }
        float s_lo = d1bias, s_hi = d1bias;
#pragma unroll
        for (int o = 0; o < 10; o++) {
            float hlo, hhi; upk(h[o], hlo, hhi);
            s_lo = fmaf(fmaxf(hlo + d2bs[o], 0.0f), d1ws[o], s_lo);
            s_hi = fmaf(fmaxf(hhi + d2bs[o], 0.0f), d1ws[o], s_hi);
        }
        float accA = 10.0f * s_lo - 6.0f;
        float accB = 10.0f * s_hi - 6.0f;

        // ---- E: state update + output ----
        if (lane == 0) {
            float pAlo, pBlo, sAlo, sBlo;
            upk(posb[(head + 24) & 31], pAlo, pBlo);
            upk(spdb[(head + 24) & 31], sAlo, sBlo);
            float npA = pAlo + 0.1f * sAlo;
            float nsA = sAlo + 0.1f * accA;
            float npB = pBlo + 0.1f * sBlo;
            float nsB = sBlo + 0.1f * accB;
            ((float2*)out)[(size_t)vA * nt + t] = make_float2(npA, nsA);
            if (hasB)
                ((float2*)out)[(size_t)vB * nt + t] = make_float2(npB, nsB);
            posb[(head + 25) & 31] = pk(npA, npB);
            spdb[(head + 25) & 31] = pk(nsA, nsB);
        }
        head = (head + 1) & 31;
        __syncwarp();
    };

    for (int t = 0; t < nt; t += 2) {
        stepf(t,     lnE0, lnE1);   // even parity
        stepf(t + 1, lnO0, lnO1);   // odd parity
    }
}

extern "C" void kernel_launch(void* const* d_in, const int* in_sizes, int n_in,
                              void* d_out, int out_size) {
    const float* lead = (const float*)d_in[0];
    const float* curs = (const float*)d_in[1];
    // d_in[2] = mask : unused by the reference
    const float* w1  = (const float*)d_in[3];
    const float* b1  = (const float*)d_in[4];
    const float* w2  = (const float*)d_in[5];
    const float* b2  = (const float*)d_in[6];
    const float* d2w = (const float*)d_in[7];
    const float* d2b = (const float*)d_in[8];
    const float* d1w = (const float*)d_in[9];
    const float* d1b = (const float*)d_in[10];

    int nveh = in_sizes[1] / (2 * PAST);
    int lead_len = in_sizes[0] / (nveh * 2);
    int nt = out_size / (nveh * 2);

    cudaFuncSetAttribute(rnncf_kernel, cudaFuncAttributeMaxDynamicSharedMemorySize, SMEM_BYTES);

    int pairs = (nveh + 1) / 2;
    int blocks = (pairs + WPB - 1) / WPB;
    rnncf_kernel<<<blocks, THREADS, SMEM_BYTES>>>(
        lead, curs, w1, b1, w2, b2, d2w, d2b, d1w, d1b,
        (float*)d_out, nveh, nt, lead_len);
}

// round 7
// speedup vs baseline: 2.5595x; 1.0727x over previous
#include <cuda_runtime.h>

// RNN car-following model, GB300 sm_103a — round 5.
// 4 vehicles per warp: two f32x2 packs (V2 = {a,b}); weights read once per warp
// serve 4 vehicles (halves per-vehicle smem-crossbar traffic, the R4 binder).
// Per-vehicle smem data is pack-interleaved so one LDS.128 broadcast feeds both
// packs. Incremental conv2 (period-2 shift identity) kept from R4, bit-exact.

#define PAST 25
#define WPB 7
#define THREADS (WPB * 32)

typedef unsigned long long u64;

__device__ __forceinline__ u64 pk(float lo, float hi) {
    u64 r; asm("mov.b64 %0, {%1, %2};" : "=l"(r) : "f"(lo), "f"(hi)); return r;
}
__device__ __forceinline__ void upk(u64 v, float& lo, float& hi) {
    asm("mov.b64 {%0, %1}, %2;" : "=f"(lo), "=f"(hi) : "l"(v));
}
__device__ __forceinline__ u64 f2fma(u64 a, u64 b, u64 c) {
    u64 d; asm("fma.rn.f32x2 %0, %1, %2, %3;" : "=l"(d) : "l"(a), "l"(b), "l"(c)); return d;
}
__device__ __forceinline__ u64 f2add(u64 a, u64 b) {
    u64 d; asm("add.rn.f32x2 %0, %1, %2;" : "=l"(d) : "l"(a), "l"(b)); return d;
}
__device__ __forceinline__ u64 f2mul(u64 a, u64 b) {
    u64 d; asm("mul.rn.f32x2 %0, %1, %2;" : "=l"(d) : "l"(a), "l"(b)); return d;
}

struct V2 { u64 a, b; };    // a = vehicles {0,1}, b = vehicles {2,3}

__device__ __forceinline__ V2 v2fma(V2 x, u64 w, V2 c) {    // shared weight
    return { f2fma(x.a, w, c.a), f2fma(x.b, w, c.b) };
}
__device__ __forceinline__ V2 v2add(V2 x, V2 y) { return { f2add(x.a, y.a), f2add(x.b, y.b) }; }
__device__ __forceinline__ V2 ld2(const u64* p) {
    ulonglong2 q = *(const ulonglong2*)p; return { q.x, q.y };
}
__device__ __forceinline__ void st2(u64* p, V2 v) {
    *(ulonglong2*)p = make_ulonglong2(v.a, v.b);
}
__device__ __forceinline__ V2 v2zero() { return { 0ull, 0ull }; }

// ---- shared layout (bytes) ----
// w2s   f32[6144]  @0      (24576)  conv2 weights scalar, [ci][k][co]
// d2ws  f32[3840]  @24576  (15360)  dense 384x10 scalar, layout [o][i]
// w1s   f32[288]   @39936  (1152)
// b1s   f32[32]    @41088
// b2s   f32[64]    @41216
// d2bs  f32[16]    @41472
// d1ws  f32[16]    @41536  (w[0..9], bias at [15])
// per-warp @41600, stride 9216 B (u64 units, pack-interleaved: entry e -> [2e],[2e+1]):
//   xs     96  entries (3x32 channel-major; slots 25..31 zeroed once)
//   pool1T 416 entries ([j][ci] : 13 x 32)
//   posb   32, spdb 32  circular
#define OFF_W2S   0
#define OFF_D2WS  24576
#define OFF_W1    39936
#define OFF_B1    41088
#define OFF_B2    41216
#define OFF_D2B   41472
#define OFF_D1W   41536
#define OFF_WARP  41600
#define WARP_BYTES 9216
#define SMEM_BYTES (OFF_WARP + WPB * WARP_BYTES)

__global__ __launch_bounds__(THREADS, 1)
void rnncf_kernel(const float* __restrict__ lead,   // [nveh][lead_len][2]
                  const float* __restrict__ curst,  // [nveh][25][2]
                  const float* __restrict__ w1,     // [3][3][32]
                  const float* __restrict__ b1,     // [32]
                  const float* __restrict__ w2,     // [3][32][64]
                  const float* __restrict__ b2,     // [64]
                  const float* __restrict__ d2w,    // [384][10]
                  const float* __restrict__ d2b,    // [10]
                  const float* __restrict__ d1w,    // [10][1]
                  const float* __restrict__ d1b,    // [1]
                  float* __restrict__ out,          // [nveh][nt][2]
                  int nveh, int nt, int lead_len)
{
    extern __shared__ __align__(16) unsigned char smraw[];
    float* w2s  = (float*)(smraw + OFF_W2S);
    float* d2ws = (float*)(smraw + OFF_D2WS);
    float* w1s  = (float*)(smraw + OFF_W1);
    float* b1s  = (float*)(smraw + OFF_B1);
    float* b2s  = (float*)(smraw + OFF_B2);
    float* d2bs = (float*)(smraw + OFF_D2B);
    float* d1ws = (float*)(smraw + OFF_D1W);

    const int tid = threadIdx.x;

    // ---- stage weights ----
    for (int i = tid; i < 6144; i += THREADS) {
        int co = i & 63; int r = i >> 6; int ci = r / 3; int k = r - ci * 3;
        w2s[i] = w2[(k * 32 + ci) * 64 + co];       // -> [ci][k][co]
    }
    for (int i = tid; i < 3840; i += THREADS) {
        int o = i / 384; int r = i - o * 384;       // [o][i]
        d2ws[i] = d2w[r * 10 + o];
    }
    for (int i = tid; i < 288; i += THREADS) w1s[i] = w1[i];
    for (int i = tid; i < 32;  i += THREADS) b1s[i] = b1[i];
    for (int i = tid; i < 64;  i += THREADS) b2s[i] = b2[i];
    if (tid < 10) d2bs[tid] = d2b[tid];
    if (tid < 10) d1ws[tid] = d1w[tid];
    if (tid == 0) d1ws[15] = d1b[0];
    __syncthreads();

    const int warp = tid >> 5;
    const int lane = tid & 31;
    const int nquads = (nveh + 3) >> 2;
    const int quad = blockIdx.x * WPB + warp;
    if (quad >= nquads) return;
    const int vA = 4 * quad;
    const int vB = min(vA + 1, nveh - 1);
    const int vC = min(vA + 2, nveh - 1);
    const int vD = min(vA + 3, nveh - 1);
    const bool hasB = (vA + 1) < nveh, hasC = (vA + 2) < nveh, hasD = (vA + 3) < nveh;

    u64* warpbuf = (u64*)(smraw + OFF_WARP + warp * WARP_BYTES);
    u64* xs     = warpbuf;           // 96 entries  -> 192 u64
    u64* pool1T = xs + 192;          // 416 entries -> 832 u64
    u64* posb   = pool1T + 832;      // 32 entries  -> 64 u64
    u64* spdb   = posb + 64;         // 32 entries  -> 64 u64

    const float2* leadA = (const float2*)(lead + (size_t)vA * lead_len * 2);
    const float2* leadB = (const float2*)(lead + (size_t)vB * lead_len * 2);
    const float2* leadC = (const float2*)(lead + (size_t)vC * lead_len * 2);
    const float2* leadD = (const float2*)(lead + (size_t)vD * lead_len * 2);

    if (lane < PAST) {
        float2 cA = ((const float2*)curst)[vA * PAST + lane];
        float2 cB = ((const float2*)curst)[vB * PAST + lane];
        float2 cC = ((const float2*)curst)[vC * PAST + lane];
        float2 cD = ((const float2*)curst)[vD * PAST + lane];
        st2(&posb[2 * lane], V2{ pk(cA.x, cB.x), pk(cC.x, cD.x) });
        st2(&spdb[2 * lane], V2{ pk(cA.y, cB.y), pk(cC.y, cD.y) });
    } else {
        st2(&xs[2 * lane], v2zero());
        st2(&xs[2 * (32 + lane)], v2zero());
        st2(&xs[2 * (64 + lane)], v2zero());
    }

    const u64 b1p  = pk(b1s[lane], b1s[lane]);
    const float b2r0 = b2s[lane];
    const float b2r1 = b2s[lane + 32];
    const float d1bias = d1ws[15];

    const u64 C_NEG1 = pk(-1.0f, -1.0f);
    const u64 C_HD   = pk(1.0f / 200.0f, 1.0f / 200.0f);
    const u64 C_V    = pk(1.0f / 40.0f,  1.0f / 40.0f);

    int head = 0;
    __syncwarp();

    // conv1 weights packed: w1r[k*3+ci]  (shared by both packs)
    u64 w1r[9];
#pragma unroll
    for (int q = 0; q < 9; q++) { float w = w1s[q * 32 + lane]; w1r[q] = pk(w, w); }

    // delay lines: conv2_{t-2}[2..9] per parity, per co-half (V2 = 4 vehicles)
    V2 lnE0[8], lnE1[8], lnO0[8], lnO1[8];

    // conv1 at one position + relu (packed)
    auto conv1_at = [&](V2 xm0, V2 xm1, V2 xm2, V2 x00, V2 x01, V2 x02,
                        V2 xp0, V2 xp1, V2 xp2) -> V2 {
        V2 val = { b1p, b1p };
        val = v2fma(xm0, w1r[0], val); val = v2fma(xm1, w1r[1], val); val = v2fma(xm2, w1r[2], val);
        val = v2fma(x00, w1r[3], val); val = v2fma(x01, w1r[4], val); val = v2fma(x02, w1r[5], val);
        val = v2fma(xp0, w1r[6], val); val = v2fma(xp1, w1r[7], val); val = v2fma(xp2, w1r[8], val);
        float a0, a1, b0, b1v;
        upk(val.a, a0, a1); upk(val.b, b0, b1v);
        return { pk(fmaxf(a0, 0.f), fmaxf(a1, 0.f)), pk(fmaxf(b0, 0.f), fmaxf(b1v, 0.f)) };
    };
    auto v2max = [&](V2 x, V2 y) -> V2 {
        float xa0, xa1, xb0, xb1, ya0, ya1, yb0, yb1;
        upk(x.a, xa0, xa1); upk(x.b, xb0, xb1);
        upk(y.a, ya0, ya1); upk(y.b, yb0, yb1);
        return { pk(fmaxf(xa0, ya0), fmaxf(xa1, ya1)), pk(fmaxf(xb0, yb0), fmaxf(xb1, yb1)) };
    };

    auto stepf = [&](int t, V2 (&l0)[8], V2 (&l1)[8]) {
        // ---- A: packed input window ----
        if (lane < PAST) {
            int s = t + lane;
            float2 lA = leadA[s], lB = leadB[s], lC = leadC[s], lD = leadD[s];
            V2 lp = { pk(lA.x, lB.x), pk(lC.x, lD.x) };
            V2 ls = { pk(lA.y, lB.y), pk(lC.y, lD.y) };
            V2 pw = ld2(&posb[2 * ((head + lane) & 31)]);
            V2 sw = ld2(&spdb[2 * ((head + lane) & 31)]);
            V2 hd = { f2mul(f2fma(pw.a, C_NEG1, lp.a), C_HD),
                      f2mul(f2fma(pw.b, C_NEG1, lp.b), C_HD) };
            st2(&xs[2 * lane], hd);
            st2(&xs[2 * (32 + lane)], V2{ f2mul(sw.a, C_V), f2mul(sw.b, C_V) });
            st2(&xs[2 * (64 + lane)], V2{ f2mul(ls.a, C_V), f2mul(ls.b, C_V) });
        }
        __syncwarp();

        V2 c0[11], c1[11];   // conv2 pre-bias outputs (co=lane / co=lane+32)

        if (t >= 2) {
            // ---- conv1 partial: pool1 j in {0,1,2} and {8..12} ----
            {   // w = 0..5 -> j=0,1,2
                V2 xm0 = v2zero(), xm1 = v2zero(), xm2 = v2zero();
                V2 x00 = ld2(&xs[0]), x01 = ld2(&xs[64]), x02 = ld2(&xs[128]);
                V2 prev = v2zero();
#pragma unroll
                for (int w = 0; w < 6; w++) {
                    V2 xp0 = ld2(&xs[2 * (w + 1)]), xp1 = ld2(&xs[2 * (33 + w)]), xp2 = ld2(&xs[2 * (65 + w)]);
                    V2 val = conv1_at(xm0, xm1, xm2, x00, x01, x02, xp0, xp1, xp2);
                    if ((w & 1) == 0) prev = val;
                    else st2(&pool1T[2 * ((w >> 1) * 32 + lane)], v2max(prev, val));
                    xm0 = x00; xm1 = x01; xm2 = x02;
                    x00 = xp0; x01 = xp1; x02 = xp2;
                }
            }
            {   // w = 16..24 -> j=8..12
                V2 xm0 = ld2(&xs[2 * 15]), xm1 = ld2(&xs[2 * 47]), xm2 = ld2(&xs[2 * 79]);
                V2 x00 = ld2(&xs[2 * 16]), x01 = ld2(&xs[2 * 48]), x02 = ld2(&xs[2 * 80]);
                V2 prev = v2zero();
#pragma unroll
                for (int w = 16; w < 25; w++) {
                    V2 xp0 = ld2(&xs[2 * (w + 1)]), xp1 = ld2(&xs[2 * (33 + w)]), xp2 = ld2(&xs[2 * (65 + w)]);
                    V2 val = conv1_at(xm0, xm1, xm2, x00, x01, x02, xp0, xp1, xp2);
                    if ((w & 1) == 0) {
                        if (w == 24) st2(&pool1T[2 * (12 * 32 + lane)], val);
                        else prev = val;
                    } else {
                        st2(&pool1T[2 * ((w >> 1) * 32 + lane)], v2max(prev, val));
                    }
                    xm0 = x00; xm1 = x01; xm2 = x02;
                    x00 = xp0; x01 = xp1; x02 = xp2;
                }
            }
            __syncwarp();

            // ---- conv2 incremental: recompute q = 0, 9, 10 only ----
            V2 n0a = v2zero(), n9a = v2zero(), n10a = v2zero();
            V2 n0b = v2zero(), n9b = v2zero(), n10b = v2zero();
#pragma unroll 4
            for (int ci = 0; ci < 32; ci++) {
                V2 p0  = ld2(&pool1T[2 * ci]);
                V2 p1  = ld2(&pool1T[2 * (32 + ci)]);
                V2 p2  = ld2(&pool1T[2 * (64 + ci)]);
                V2 p9  = ld2(&pool1T[2 * (288 + ci)]);
                V2 p10 = ld2(&pool1T[2 * (320 + ci)]);
                V2 p11 = ld2(&pool1T[2 * (352 + ci)]);
                V2 p12 = ld2(&pool1T[2 * (384 + ci)]);
                const float* wrow = &w2s[ci * 192];
                float s0 = wrow[lane],      s1 = wrow[64 + lane],  s2 = wrow[128 + lane];
                float s3 = wrow[32 + lane], s4 = wrow[96 + lane],  s5 = wrow[160 + lane];
                u64 wa0 = pk(s0, s0), wa1 = pk(s1, s1), wa2 = pk(s2, s2);
                u64 wb0 = pk(s3, s3), wb1 = pk(s4, s4), wb2 = pk(s5, s5);
                n0a  = v2fma(p0,  wa0, n0a);  n0a  = v2fma(p1,  wa1, n0a);  n0a  = v2fma(p2,  wa2, n0a);
                n9a  = v2fma(p9,  wa0, n9a);  n9a  = v2fma(p10, wa1, n9a);  n9a  = v2fma(p11, wa2, n9a);
                n10a = v2fma(p10, wa0, n10a); n10a = v2fma(p11, wa1, n10a); n10a = v2fma(p12, wa2, n10a);
                n0b  = v2fma(p0,  wb0, n0b);  n0b  = v2fma(p1,  wb1, n0b);  n0b  = v2fma(p2,  wb2, n0b);
                n9b  = v2fma(p9,  wb0, n9b);  n9b  = v2fma(p10, wb1, n9b);  n9b  = v2fma(p11, wb2, n9b);
                n10b = v2fma(p10, wb0, n10b); n10b = v2fma(p11, wb1, n10b); n10b = v2fma(p12, wb2, n10b);
            }
            c0[0] = n0a; c1[0] = n0b;
#pragma unroll
            for (int q = 1; q <= 8; q++) { c0[q] = l0[q - 1]; c1[q] = l1[q - 1]; }
            c0[9] = n9a; c0[10] = n10a; c1[9] = n9b; c1[10] = n10b;
#pragma unroll
            for (int j = 0; j < 7; j++) { l0[j] = l0[j + 1]; l1[j] = l1[j + 1]; }
            l0[7] = n9a; l1[7] = n9b;
        } else {
            // ---- FULL path (t = 0, 1) ----
            {
                V2 xm0 = v2zero(), xm1 = v2zero(), xm2 = v2zero();
                V2 x00 = ld2(&xs[0]), x01 = ld2(&xs[64]), x02 = ld2(&xs[128]);
                V2 prev = v2zero();
#pragma unroll
                for (int w = 0; w < 25; w++) {
                    V2 xp0 = ld2(&xs[2 * (w + 1)]), xp1 = ld2(&xs[2 * (33 + w)]), xp2 = ld2(&xs[2 * (65 + w)]);
                    V2 val = conv1_at(xm0, xm1, xm2, x00, x01, x02, xp0, xp1, xp2);
                    if ((w & 1) == 0) {
                        if (w == 24) st2(&pool1T[2 * (12 * 32 + lane)], val);
                        else prev = val;
                    } else {
                        st2(&pool1T[2 * ((w >> 1) * 32 + lane)], v2max(prev, val));
                    }
                    xm0 = x00; xm1 = x01; xm2 = x02;
                    x00 = xp0; x01 = xp1; x02 = xp2;
                }
            }
            __syncwarp();
            V2 a0[11], a1[11];
#pragma unroll
            for (int q = 0; q < 11; q++) { a0[q] = v2zero(); a1[q] = v2zero(); }
#pragma unroll 2
            for (int ci = 0; ci < 32; ci++) {
                V2 p[13];
#pragma unroll
                for (int j = 0; j < 13; j++) p[j] = ld2(&pool1T[2 * (j * 32 + ci)]);
                const float* wrow = &w2s[ci * 192];
                float s0 = wrow[lane],      s1 = wrow[64 + lane],  s2 = wrow[128 + lane];
                float s3 = wrow[32 + lane], s4 = wrow[96 + lane],  s5 = wrow[160 + lane];
                u64 wa0 = pk(s0, s0), wa1 = pk(s1, s1), wa2 = pk(s2, s2);
                u64 wb0 = pk(s3, s3), wb1 = pk(s4, s4), wb2 = pk(s5, s5);
#pragma unroll
                for (int q = 0; q < 11; q++) {
                    a0[q] = v2fma(p[q], wa0, a0[q]);
                    a0[q] = v2fma(p[q + 1], wa1, a0[q]);
                    a0[q] = v2fma(p[q + 2], wa2, a0[q]);
                    a1[q] = v2fma(p[q], wb0, a1[q]);
                    a1[q] = v2fma(p[q + 1], wb1, a1[q]);
                    a1[q] = v2fma(p[q + 2], wb2, a1[q]);
                }
            }
#pragma unroll
            for (int q = 0; q < 11; q++) { c0[q] = a0[q]; c1[q] = a1[q]; }
#pragma unroll
            for (int j = 0; j < 8; j++) { l0[j] = a0[j + 2]; l1[j] = a1[j + 2]; }
        }

        // ---- pool2 (bias + relu + maxpool2) -> registers ----
        V2 pl[6], ph[6];
        const u64 b2p0 = pk(b2r0, b2r0), b2p1 = pk(b2r1, b2r1);
#pragma unroll
        for (int pp = 0; pp < 6; pp++) {
            V2 r0 = { f2add(c0[2 * pp].a, b2p0), f2add(c0[2 * pp].b, b2p0) };
            V2 r1 = { f2add(c1[2 * pp].a, b2p1), f2add(c1[2 * pp].b, b2p1) };
            r0 = v2max(r0, v2zero());
            r1 = v2max(r1, v2zero());
            if (pp < 5) {
                V2 e1 = { f2add(c0[2 * pp + 1].a, b2p0), f2add(c0[2 * pp + 1].b, b2p0) };
                V2 f1 = { f2add(c1[2 * pp + 1].a, b2p1), f2add(c1[2 * pp + 1].b, b2p1) };
                r0 = v2max(r0, v2max(e1, v2zero()));
                r1 = v2max(r1, v2max(f1, v2zero()));
            }
            pl[pp] = r0;   // i = pp*64 + lane
            ph[pp] = r1;   // i = pp*64 + 32 + lane
        }

        // ---- dense 384->10 (scalar weights [o][i], shared across packs) ----
        V2 h[10];
#pragma unroll
        for (int o = 0; o < 10; o++) h[o] = v2zero();
#pragma unroll
        for (int pp = 0; pp < 6; pp++) {
#pragma unroll
            for (int half = 0; half < 2; half++) {
                V2 xv = half ? ph[pp] : pl[pp];
                int i = (2 * pp + half) * 32 + lane;
#pragma unroll
                for (int o = 0; o < 10; o++) {
                    float w = d2ws[o * 384 + i];
                    h[o] = v2fma(xv, pk(w, w), h[o]);
                }
            }
        }
#pragma unroll
        for (int off = 16; off > 0; off >>= 1) {
#pragma unroll
            for (int o = 0; o < 10; o++) {
                h[o].a = f2add(h[o].a, __shfl_xor_sync(0xffffffffu, h[o].a, off));
                h[o].b = f2add(h[o].b, __shfl_xor_sync(0xffffffffu, h[o].b, off));
            }
        }
        float sA = d1bias, sB = d1bias, sC = d1bias, sD = d1bias;
#pragma unroll
        for (int o = 0; o < 10; o++) {
            float hA, hB, hC, hD;
            upk(h[o].a, hA, hB); upk(h[o].b, hC, hD);
            float bo = d2bs[o], wo = d1ws[o];
            sA = fmaf(fmaxf(hA + bo, 0.0f), wo, sA);
            sB = fmaf(fmaxf(hB + bo, 0.0f), wo, sB);
            sC = fmaf(fmaxf(hC + bo, 0.0f), wo, sC);
            sD = fmaf(fmaxf(hD + bo, 0.0f), wo, sD);
        }
        float accA = 10.0f * sA - 6.0f;
        float accB = 10.0f * sB - 6.0f;
        float accC = 10.0f * sC - 6.0f;
        float accD = 10.0f * sD - 6.0f;

        // ---- E: state update + output ----
        if (lane == 0) {
            V2 pv = ld2(&posb[2 * ((head + 24) & 31)]);
            V2 sv = ld2(&spdb[2 * ((head + 24) & 31)]);
            float pA, pB, pC, pD, qA, qB, qC, qD;
            upk(pv.a, pA, pB); upk(pv.b, pC, pD);
            upk(sv.a, qA, qB); upk(sv.b, qC, qD);
            float npA = pA + 0.1f * qA, nsA = qA + 0.1f * accA;
            float npB = pB + 0.1f * qB, nsB = qB + 0.1f * accB;
            float npC = pC + 0.1f * qC, nsC = qC + 0.1f * accC;
            float npD = pD + 0.1f * qD, nsD = qD + 0.1f * accD;
            ((float2*)out)[(size_t)vA * nt + t] = make_float2(npA, nsA);
            if (hasB) ((float2*)out)[(size_t)vB * nt + t] = make_float2(npB, nsB);
            if (hasC) ((float2*)out)[(size_t)vC * nt + t] = make_float2(npC, nsC);
            if (hasD) ((float2*)out)[(size_t)vD * nt + t] = make_float2(npD, nsD);
            st2(&posb[2 * ((head + 25) & 31)], V2{ pk(npA, npB), pk(npC, npD) });
            st2(&spdb[2 * ((head + 25) & 31)], V2{ pk(nsA, nsB), pk(nsC, nsD) });
        }
        head = (head + 1) & 31;
        __syncwarp();
    };

    for (int t = 0; t < nt; t += 2) {
        stepf(t,     lnE0, lnE1);   // even parity
        stepf(t + 1, lnO0, lnO1);   // odd parity
    }
}

extern "C" void kernel_launch(void* const* d_in, const int* in_sizes, int n_in,
                              void* d_out, int out_size) {
    const float* lead = (const float*)d_in[0];
    const float* curs = (const float*)d_in[1];
    // d_in[2] = mask : unused by the reference
    const float* w1  = (const float*)d_in[3];
    const float* b1  = (const float*)d_in[4];
    const float* w2  = (const float*)d_in[5];
    const float* b2  = (const float*)d_in[6];
    const float* d2w = (const float*)d_in[7];
    const float* d2b = (const float*)d_in[8];
    const float* d1w = (const float*)d_in[9];
    const float* d1b = (const float*)d_in[10];

    int nveh = in_sizes[1] / (2 * PAST);
    int lead_len = in_sizes[0] / (nveh * 2);
    int nt = out_size / (nveh * 2);

    cudaFuncSetAttribute(rnncf_kernel, cudaFuncAttributeMaxDynamicSharedMemorySize, SMEM_BYTES);

    int quads = (nveh + 3) / 4;
    int blocks = (quads + WPB - 1) / WPB;
    rnncf_kernel<<<blocks, THREADS, SMEM_BYTES>>>(
        lead, curs, w1, b1, w2, b2, d2w, d2b, d1w, d1b,
        (float*)d_out, nveh, nt, lead_len);
}

// round 8
// speedup vs baseline: 2.9276x; 1.1438x over previous
#include <cuda_runtime.h>

// RNN car-following model, GB300 sm_103a — round 6.
// 4 vehicles/warp (two f32x2 packs). Incremental conv2 taken further:
// fresh work per step is only q0 (direct) and four tap-sums T0[11],T1[11],
// T2[11],T2[12]; q9/q10 are reassembled from T-history via the shift identity
//   p_t[j] = p_{t-2}[j+1]  (j in 1..10):
//   q9  = T0[11]@t-4 + T1[11]@t-2 + T2[11]@t
//   q10 = T0[11]@t-2 + T1[11]@t   + T2[12]@t
// q1..q8 from the conv2 delay line as before. conv1 shrinks to 9 positions.
// T histories live in a small per-warp smem ring (lane-private, no syncs).

#define PAST 25
#define WPB 8
#define THREADS (WPB * 32)

typedef unsigned long long u64;

__device__ __forceinline__ u64 pk(float lo, float hi) {
    u64 r; asm("mov.b64 %0, {%1, %2};" : "=l"(r) : "f"(lo), "f"(hi)); return r;
}
__device__ __forceinline__ void upk(u64 v, float& lo, float& hi) {
    asm("mov.b64 {%0, %1}, %2;" : "=f"(lo), "=f"(hi) : "l"(v));
}
__device__ __forceinline__ u64 f2fma(u64 a, u64 b, u64 c) {
    u64 d; asm("fma.rn.f32x2 %0, %1, %2, %3;" : "=l"(d) : "l"(a), "l"(b), "l"(c)); return d;
}
__device__ __forceinline__ u64 f2add(u64 a, u64 b) {
    u64 d; asm("add.rn.f32x2 %0, %1, %2;" : "=l"(d) : "l"(a), "l"(b)); return d;
}
__device__ __forceinline__ u64 f2mul(u64 a, u64 b) {
    u64 d; asm("mul.rn.f32x2 %0, %1, %2;" : "=l"(d) : "l"(a), "l"(b)); return d;
}

struct V2 { u64 a, b; };    // a = vehicles {0,1}, b = vehicles {2,3}

__device__ __forceinline__ V2 v2fma(V2 x, u64 w, V2 c) {
    return { f2fma(x.a, w, c.a), f2fma(x.b, w, c.b) };
}
__device__ __forceinline__ V2 v2add(V2 x, V2 y) { return { f2add(x.a, y.a), f2add(x.b, y.b) }; }
__device__ __forceinline__ V2 ld2(const u64* p) {
    ulonglong2 q = *(const ulonglong2*)p; return { q.x, q.y };
}
__device__ __forceinline__ void st2(u64* p, V2 v) {
    *(ulonglong2*)p = make_ulonglong2(v.a, v.b);
}
__device__ __forceinline__ V2 v2zero() { return { 0ull, 0ull }; }

// ---- shared layout (bytes) ----
// w2s   f32[6144]  @0      (24576)  conv2 weights scalar, [ci][k][co]
// d2ws  f32[3840]  @24576  (15360)  dense 384x10 scalar, layout [o][i]
// w1s   f32[288]   @39936
// b1s   f32[32]    @41088
// b2s   f32[64]    @41216
// d2bs  f32[16]    @41472
// d1ws  f32[16]    @41536  (w[0..9], bias at [15])
// per-warp @41600, stride 15360 B (u64 units; entries pack-interleaved):
//   xs     96 entries  (192 u64)
//   pool1T 416 entries (832 u64) [j][ci]
//   posb   32 (64), spdb 32 (64)
//   Tring  12 V2-slots x 32 lanes (768 u64)
//     slots: T0 ring = ((p*2+half)*2+s), s=u&1, depth 2  -> v in [0,8)
//            T1 ring = 8 + p*2 + half, depth 1           -> v in [8,12)
#define OFF_W2S   0
#define OFF_D2WS  24576
#define OFF_W1    39936
#define OFF_B1    41088
#define OFF_B2    41216
#define OFF_D2B   41472
#define OFF_D1W   41536
#define OFF_WARP  41600
#define WARP_BYTES 15360
#define SMEM_BYTES (OFF_WARP + WPB * WARP_BYTES)

__global__ __launch_bounds__(THREADS, 1)
void rnncf_kernel(const float* __restrict__ lead,   // [nveh][lead_len][2]
                  const float* __restrict__ curst,  // [nveh][25][2]
                  const float* __restrict__ w1,     // [3][3][32]
                  const float* __restrict__ b1,     // [32]
                  const float* __restrict__ w2,     // [3][32][64]
                  const float* __restrict__ b2,     // [64]
                  const float* __restrict__ d2w,    // [384][10]
                  const float* __restrict__ d2b,    // [10]
                  const float* __restrict__ d1w,    // [10][1]
                  const float* __restrict__ d1b,    // [1]
                  float* __restrict__ out,          // [nveh][nt][2]
                  int nveh, int nt, int lead_len)
{
    extern __shared__ __align__(16) unsigned char smraw[];
    float* w2s  = (float*)(smraw + OFF_W2S);
    float* d2ws = (float*)(smraw + OFF_D2WS);
    float* w1s  = (float*)(smraw + OFF_W1);
    float* b1s  = (float*)(smraw + OFF_B1);
    float* b2s  = (float*)(smraw + OFF_B2);
    float* d2bs = (float*)(smraw + OFF_D2B);
    float* d1ws = (float*)(smraw + OFF_D1W);

    const int tid = threadIdx.x;

    // ---- stage weights ----
    for (int i = tid; i < 6144; i += THREADS) {
        int co = i & 63; int r = i >> 6; int ci = r / 3; int k = r - ci * 3;
        w2s[i] = w2[(k * 32 + ci) * 64 + co];       // -> [ci][k][co]
    }
    for (int i = tid; i < 3840; i += THREADS) {
        int o = i / 384; int r = i - o * 384;       // [o][i]
        d2ws[i] = d2w[r * 10 + o];
    }
    for (int i = tid; i < 288; i += THREADS) w1s[i] = w1[i];
    for (int i = tid; i < 32;  i += THREADS) b1s[i] = b1[i];
    for (int i = tid; i < 64;  i += THREADS) b2s[i] = b2[i];
    if (tid < 10) d2bs[tid] = d2b[tid];
    if (tid < 10) d1ws[tid] = d1w[tid];
    if (tid == 0) d1ws[15] = d1b[0];
    __syncthreads();

    const int warp = tid >> 5;
    const int lane = tid & 31;
    const int nquads = (nveh + 3) >> 2;
    const int quad = blockIdx.x * WPB + warp;
    if (quad >= nquads) return;
    const int vA = 4 * quad;
    const int vB = min(vA + 1, nveh - 1);
    const int vC = min(vA + 2, nveh - 1);
    const int vD = min(vA + 3, nveh - 1);
    const bool hasB = (vA + 1) < nveh, hasC = (vA + 2) < nveh, hasD = (vA + 3) < nveh;

    u64* warpbuf = (u64*)(smraw + OFF_WARP + warp * WARP_BYTES);
    u64* xs     = warpbuf;           // 192 u64
    u64* pool1T = xs + 192;          // 832 u64
    u64* posb   = pool1T + 832;      // 64 u64
    u64* spdb   = posb + 64;         // 64 u64
    u64* Tring  = spdb + 64;         // 768 u64

    const float2* leadA = (const float2*)(lead + (size_t)vA * lead_len * 2);
    const float2* leadB = (const float2*)(lead + (size_t)vB * lead_len * 2);
    const float2* leadC = (const float2*)(lead + (size_t)vC * lead_len * 2);
    const float2* leadD = (const float2*)(lead + (size_t)vD * lead_len * 2);

    if (lane < PAST) {
        float2 cA = ((const float2*)curst)[vA * PAST + lane];
        float2 cB = ((const float2*)curst)[vB * PAST + lane];
        float2 cC = ((const float2*)curst)[vC * PAST + lane];
        float2 cD = ((const float2*)curst)[vD * PAST + lane];
        st2(&posb[2 * lane], V2{ pk(cA.x, cB.x), pk(cC.x, cD.x) });
        st2(&spdb[2 * lane], V2{ pk(cA.y, cB.y), pk(cC.y, cD.y) });
    } else {
        st2(&xs[2 * lane], v2zero());
        st2(&xs[2 * (32 + lane)], v2zero());
        st2(&xs[2 * (64 + lane)], v2zero());
    }

    const u64 b1p  = pk(b1s[lane], b1s[lane]);
    const float b2r0 = b2s[lane];
    const float b2r1 = b2s[lane + 32];
    const float d1bias = d1ws[15];

    const u64 C_NEG1 = pk(-1.0f, -1.0f);
    const u64 C_HD   = pk(1.0f / 200.0f, 1.0f / 200.0f);
    const u64 C_V    = pk(1.0f / 40.0f,  1.0f / 40.0f);

    int head = 0;
    __syncwarp();

    u64 w1r[9];
#pragma unroll
    for (int q = 0; q < 9; q++) { float w = w1s[q * 32 + lane]; w1r[q] = pk(w, w); }

    // conv2 delay lines: conv2_{t-2}[2..9] per parity, per co-half
    V2 lnE0[8], lnE1[8], lnO0[8], lnO1[8];

    auto conv1_at = [&](V2 xm0, V2 xm1, V2 xm2, V2 x00, V2 x01, V2 x02,
                        V2 xp0, V2 xp1, V2 xp2) -> V2 {
        V2 val = { b1p, b1p };
        val = v2fma(xm0, w1r[0], val); val = v2fma(xm1, w1r[1], val); val = v2fma(xm2, w1r[2], val);
        val = v2fma(x00, w1r[3], val); val = v2fma(x01, w1r[4], val); val = v2fma(x02, w1r[5], val);
        val = v2fma(xp0, w1r[6], val); val = v2fma(xp1, w1r[7], val); val = v2fma(xp2, w1r[8], val);
        float a0, a1, b0, b1v;
        upk(val.a, a0, a1); upk(val.b, b0, b1v);
        return { pk(fmaxf(a0, 0.f), fmaxf(a1, 0.f)), pk(fmaxf(b0, 0.f), fmaxf(b1v, 0.f)) };
    };
    auto v2max = [&](V2 x, V2 y) -> V2 {
        float xa0, xa1, xb0, xb1, ya0, ya1, yb0, yb1;
        upk(x.a, xa0, xa1); upk(x.b, xb0, xb1);
        upk(y.a, ya0, ya1); upk(y.b, yb0, yb1);
        return { pk(fmaxf(xa0, ya0), fmaxf(xa1, ya1)), pk(fmaxf(xb0, yb0), fmaxf(xb1, yb1)) };
    };
    auto tsl = [&](int v) -> u64* { return &Tring[(v * 32 + lane) * 2]; };

    auto stepf = [&](int t, V2 (&l0)[8], V2 (&l1)[8]) {
        // ---- A: packed input window ----
        if (lane < PAST) {
            int s = t + lane;
            float2 lA = leadA[s], lB = leadB[s], lC = leadC[s], lD = leadD[s];
            V2 lp = { pk(lA.x, lB.x), pk(lC.x, lD.x) };
            V2 ls = { pk(lA.y, lB.y), pk(lC.y, lD.y) };
            V2 pw = ld2(&posb[2 * ((head + lane) & 31)]);
            V2 sw = ld2(&spdb[2 * ((head + lane) & 31)]);
            V2 hd = { f2mul(f2fma(pw.a, C_NEG1, lp.a), C_HD),
                      f2mul(f2fma(pw.b, C_NEG1, lp.b), C_HD) };
            st2(&xs[2 * lane], hd);
            st2(&xs[2 * (32 + lane)], V2{ f2mul(sw.a, C_V), f2mul(sw.b, C_V) });
            st2(&xs[2 * (64 + lane)], V2{ f2mul(ls.a, C_V), f2mul(ls.b, C_V) });
        }
        __syncwarp();

        V2 c0[11], c1[11];
        const int par = t & 1;
        const int u   = t >> 1;
        const int us  = u & 1;
        const int t0a_s  = ((par * 2 + 0) * 2 + us);
        const int t0a_s1 = ((par * 2 + 0) * 2 + (us ^ 1));
        const int t0b_s  = ((par * 2 + 1) * 2 + us);
        const int t0b_s1 = ((par * 2 + 1) * 2 + (us ^ 1));
        const int t1a = 8 + par * 2 + 0;
        const int t1b = 8 + par * 2 + 1;

        if (t >= 8) {
            // ---- conv1: rows j=0,1,2 (w=0..5) ----
            {
                V2 xm0 = v2zero(), xm1 = v2zero(), xm2 = v2zero();
                V2 x00 = ld2(&xs[0]), x01 = ld2(&xs[64]), x02 = ld2(&xs[128]);
                V2 prev = v2zero();
#pragma unroll
                for (int w = 0; w < 6; w++) {
                    V2 xp0 = ld2(&xs[2 * (w + 1)]), xp1 = ld2(&xs[2 * (33 + w)]), xp2 = ld2(&xs[2 * (65 + w)]);
                    V2 val = conv1_at(xm0, xm1, xm2, x00, x01, x02, xp0, xp1, xp2);
                    if ((w & 1) == 0) prev = val;
                    else st2(&pool1T[2 * ((w >> 1) * 32 + lane)], v2max(prev, val));
                    xm0 = x00; xm1 = x01; xm2 = x02;
                    x00 = xp0; x01 = xp1; x02 = xp2;
                }
            }
            // ---- conv1: rows j=11 (w=22,23), j=12 (w=24) ----
            {
                V2 xm0 = ld2(&xs[2 * 21]), xm1 = ld2(&xs[2 * 53]), xm2 = ld2(&xs[2 * 85]);
                V2 x00 = ld2(&xs[2 * 22]), x01 = ld2(&xs[2 * 54]), x02 = ld2(&xs[2 * 86]);
                V2 prev = v2zero();
#pragma unroll
                for (int w = 22; w < 25; w++) {
                    V2 xp0 = ld2(&xs[2 * (w + 1)]), xp1 = ld2(&xs[2 * (33 + w)]), xp2 = ld2(&xs[2 * (65 + w)]);
                    V2 val = conv1_at(xm0, xm1, xm2, x00, x01, x02, xp0, xp1, xp2);
                    if (w == 22) prev = val;
                    else if (w == 23) st2(&pool1T[2 * (11 * 32 + lane)], v2max(prev, val));
                    else st2(&pool1T[2 * (12 * 32 + lane)], val);
                    xm0 = x00; xm1 = x01; xm2 = x02;
                    x00 = xp0; x01 = xp1; x02 = xp2;
                }
            }
            __syncwarp();

            // ---- conv2 reduced: fresh q0 + tap sums A=T0[11], B=T1[11], C=T2[11], D=T2[12] ----
            V2 q0a = v2zero(), q0b = v2zero();
            V2 A0 = v2zero(), A1 = v2zero(), B0 = v2zero(), B1 = v2zero();
            V2 Cc0 = v2zero(), Cc1 = v2zero(), D0 = v2zero(), D1 = v2zero();
#pragma unroll 4
            for (int ci = 0; ci < 32; ci++) {
                V2 p0  = ld2(&pool1T[2 * ci]);
                V2 p1  = ld2(&pool1T[2 * (32 + ci)]);
                V2 p2  = ld2(&pool1T[2 * (64 + ci)]);
                V2 p11 = ld2(&pool1T[2 * (352 + ci)]);
                V2 p12 = ld2(&pool1T[2 * (384 + ci)]);
                const float* wrow = &w2s[ci * 192];
                float s0 = wrow[lane],      s1 = wrow[64 + lane],  s2 = wrow[128 + lane];
                float s3 = wrow[32 + lane], s4 = wrow[96 + lane],  s5 = wrow[160 + lane];
                u64 wa0 = pk(s0, s0), wa1 = pk(s1, s1), wa2 = pk(s2, s2);
                u64 wb0 = pk(s3, s3), wb1 = pk(s4, s4), wb2 = pk(s5, s5);
                q0a = v2fma(p0, wa0, q0a); q0a = v2fma(p1, wa1, q0a); q0a = v2fma(p2, wa2, q0a);
                q0b = v2fma(p0, wb0, q0b); q0b = v2fma(p1, wb1, q0b); q0b = v2fma(p2, wb2, q0b);
                A0 = v2fma(p11, wa0, A0);  A1 = v2fma(p11, wb0, A1);
                B0 = v2fma(p11, wa1, B0);  B1 = v2fma(p11, wb1, B1);
                Cc0 = v2fma(p11, wa2, Cc0); Cc1 = v2fma(p11, wb2, Cc1);
                D0 = v2fma(p12, wa2, D0);  D1 = v2fma(p12, wb2, D1);
            }
            // q9 = T0@lag4 + T1@lag2 + C ; q10 = T0@lag2 + B + D
            V2 q9a  = v2add(v2add(ld2(tsl(t0a_s)),  ld2(tsl(t1a))), Cc0);
            V2 q9b  = v2add(v2add(ld2(tsl(t0b_s)),  ld2(tsl(t1b))), Cc1);
            V2 q10a = v2add(v2add(ld2(tsl(t0a_s1)), B0), D0);
            V2 q10b = v2add(v2add(ld2(tsl(t0b_s1)), B1), D1);
            st2(tsl(t0a_s), A0); st2(tsl(t0b_s), A1);
            st2(tsl(t1a), B0);   st2(tsl(t1b), B1);

            c0[0] = q0a; c1[0] = q0b;
#pragma unroll
            for (int q = 1; q <= 8; q++) { c0[q] = l0[q - 1]; c1[q] = l1[q - 1]; }
            c0[9] = q9a; c0[10] = q10a; c1[9] = q9b; c1[10] = q10b;
#pragma unroll
            for (int j = 0; j < 7; j++) { l0[j] = l0[j + 1]; l1[j] = l1[j + 1]; }
            l0[7] = q9a; l1[7] = q9b;
        } else if (t >= 2) {
            // ---- seed incremental path (computes q0,q9,q10 fresh; also stores T's) ----
            {
                V2 xm0 = v2zero(), xm1 = v2zero(), xm2 = v2zero();
                V2 x00 = ld2(&xs[0]), x01 = ld2(&xs[64]), x02 = ld2(&xs[128]);
                V2 prev = v2zero();
#pragma unroll
                for (int w = 0; w < 6; w++) {
                    V2 xp0 = ld2(&xs[2 * (w + 1)]), xp1 = ld2(&xs[2 * (33 + w)]), xp2 = ld2(&xs[2 * (65 + w)]);
                    V2 val = conv1_at(xm0, xm1, xm2, x00, x01, x02, xp0, xp1, xp2);
                    if ((w & 1) == 0) prev = val;
                    else st2(&pool1T[2 * ((w >> 1) * 32 + lane)], v2max(prev, val));
                    xm0 = x00; xm1 = x01; xm2 = x02;
                    x00 = xp0; x01 = xp1; x02 = xp2;
                }
            }
            {
                V2 xm0 = ld2(&xs[2 * 15]), xm1 = ld2(&xs[2 * 47]), xm2 = ld2(&xs[2 * 79]);
                V2 x00 = ld2(&xs[2 * 16]), x01 = ld2(&xs[2 * 48]), x02 = ld2(&xs[2 * 80]);
                V2 prev = v2zero();
#pragma unroll
                for (int w = 16; w < 25; w++) {
                    V2 xp0 = ld2(&xs[2 * (w + 1)]), xp1 = ld2(&xs[2 * (33 + w)]), xp2 = ld2(&xs[2 * (65 + w)]);
                    V2 val = conv1_at(xm0, xm1, xm2, x00, x01, x02, xp0, xp1, xp2);
                    if ((w & 1) == 0) {
                        if (w == 24) st2(&pool1T[2 * (12 * 32 + lane)], val);
                        else prev = val;
                    } else {
                        st2(&pool1T[2 * ((w >> 1) * 32 + lane)], v2max(prev, val));
                    }
                    xm0 = x00; xm1 = x01; xm2 = x02;
                    x00 = xp0; x01 = xp1; x02 = xp2;
                }
            }
            __syncwarp();

            V2 n0a = v2zero(), n9a = v2zero(), n10a = v2zero();
            V2 n0b = v2zero(), n9b = v2zero(), n10b = v2zero();
            V2 A0 = v2zero(), A1 = v2zero(), B0 = v2zero(), B1 = v2zero();
#pragma unroll 4
            for (int ci = 0; ci < 32; ci++) {
                V2 p0  = ld2(&pool1T[2 * ci]);
                V2 p1  = ld2(&pool1T[2 * (32 + ci)]);
                V2 p2  = ld2(&pool1T[2 * (64 + ci)]);
                V2 p9  = ld2(&pool1T[2 * (288 + ci)]);
                V2 p10 = ld2(&pool1T[2 * (320 + ci)]);
                V2 p11 = ld2(&pool1T[2 * (352 + ci)]);
                V2 p12 = ld2(&pool1T[2 * (384 + ci)]);
                const float* wrow = &w2s[ci * 192];
                float s0 = wrow[lane],      s1 = wrow[64 + lane],  s2 = wrow[128 + lane];
                float s3 = wrow[32 + lane], s4 = wrow[96 + lane],  s5 = wrow[160 + lane];
                u64 wa0 = pk(s0, s0), wa1 = pk(s1, s1), wa2 = pk(s2, s2);
                u64 wb0 = pk(s3, s3), wb1 = pk(s4, s4), wb2 = pk(s5, s5);
                n0a  = v2fma(p0,  wa0, n0a);  n0a  = v2fma(p1,  wa1, n0a);  n0a  = v2fma(p2,  wa2, n0a);
                n9a  = v2fma(p9,  wa0, n9a);  n9a  = v2fma(p10, wa1, n9a);  n9a  = v2fma(p11, wa2, n9a);
                n10a = v2fma(p10, wa0, n10a); n10a = v2fma(p11, wa1, n10a); n10a = v2fma(p12, wa2, n10a);
                n0b  = v2fma(p0,  wb0, n0b);  n0b  = v2fma(p1,  wb1, n0b);  n0b  = v2fma(p2,  wb2, n0b);
                n9b  = v2fma(p9,  wb0, n9b);  n9b  = v2fma(p10, wb1, n9b);  n9b  = v2fma(p11, wb2, n9b);
                n10b = v2fma(p10, wb0, n10b); n10b = v2fma(p11, wb1, n10b); n10b = v2fma(p12, wb2, n10b);
                A0 = v2fma(p11, wa0, A0); A1 = v2fma(p11, wb0, A1);
                B0 = v2fma(p11, wa1, B0); B1 = v2fma(p11, wb1, B1);
            }
            st2(tsl(t0a_s), A0); st2(tsl(t0b_s), A1);
            st2(tsl(t1a), B0);   st2(tsl(t1b), B1);

            c0[0] = n0a; c1[0] = n0b;
#pragma unroll
            for (int q = 1; q <= 8; q++) { c0[q] = l0[q - 1]; c1[q] = l1[q - 1]; }
            c0[9] = n9a; c0[10] = n10a; c1[9] = n9b; c1[10] = n10b;
#pragma unroll
            for (int j = 0; j < 7; j++) { l0[j] = l0[j + 1]; l1[j] = l1[j + 1]; }
            l0[7] = n9a; l1[7] = n9b;
        } else {
            // ---- FULL path (t = 0, 1) ----
            {
                V2 xm0 = v2zero(), xm1 = v2zero(), xm2 = v2zero();
                V2 x00 = ld2(&xs[0]), x01 = ld2(&xs[64]), x02 = ld2(&xs[128]);
                V2 prev = v2zero();
#pragma unroll
                for (int w = 0; w < 25; w++) {
                    V2 xp0 = ld2(&xs[2 * (w + 1)]), xp1 = ld2(&xs[2 * (33 + w)]), xp2 = ld2(&xs[2 * (65 + w)]);
                    V2 val = conv1_at(xm0, xm1, xm2, x00, x01, x02, xp0, xp1, xp2);
                    if ((w & 1) == 0) {
                        if (w == 24) st2(&pool1T[2 * (12 * 32 + lane)], val);
                        else prev = val;
                    } else {
                        st2(&pool1T[2 * ((w >> 1) * 32 + lane)], v2max(prev, val));
                    }
                    xm0 = x00; xm1 = x01; xm2 = x02;
                    x00 = xp0; x01 = xp1; x02 = xp2;
                }
            }
            __syncwarp();
            V2 a0[11], a1[11];
#pragma unroll
            for (int q = 0; q < 11; q++) { a0[q] = v2zero(); a1[q] = v2zero(); }
            V2 A0 = v2zero(), A1 = v2zero(), B0 = v2zero(), B1 = v2zero();
#pragma unroll 2
            for (int ci = 0; ci < 32; ci++) {
                V2 p[13];
#pragma unroll
                for (int j = 0; j < 13; j++) p[j] = ld2(&pool1T[2 * (j * 32 + ci)]);
                const float* wrow = &w2s[ci * 192];
                float s0 = wrow[lane],      s1 = wrow[64 + lane],  s2 = wrow[128 + lane];
                float s3 = wrow[32 + lane], s4 = wrow[96 + lane],  s5 = wrow[160 + lane];
                u64 wa0 = pk(s0, s0), wa1 = pk(s1, s1), wa2 = pk(s2, s2);
                u64 wb0 = pk(s3, s3), wb1 = pk(s4, s4), wb2 = pk(s5, s5);
#pragma unroll
                for (int q = 0; q < 11; q++) {
                    a0[q] = v2fma(p[q], wa0, a0[q]);
                    a0[q] = v2fma(p[q + 1], wa1, a0[q]);
                    a0[q] = v2fma(p[q + 2], wa2, a0[q]);
                    a1[q] = v2fma(p[q], wb0, a1[q]);
                    a1[q] = v2fma(p[q + 1], wb1, a1[q]);
                    a1[q] = v2fma(p[q + 2], wb2, a1[q]);
                }
                A0 = v2fma(p[11], wa0, A0); A1 = v2fma(p[11], wb0, A1);
                B0 = v2fma(p[11], wa1, B0); B1 = v2fma(p[11], wb1, B1);
            }
            st2(tsl(t0a_s), A0); st2(tsl(t0b_s), A1);
            st2(tsl(t1a), B0);   st2(tsl(t1b), B1);
#pragma unroll
            for (int q = 0; q < 11; q++) { c0[q] = a0[q]; c1[q] = a1[q]; }
#pragma unroll
            for (int j = 0; j < 8; j++) { l0[j] = a0[j + 2]; l1[j] = a1[j + 2]; }
        }

        // ---- pool2 (bias + relu + maxpool2) -> registers ----
        V2 pl[6], ph[6];
        const u64 b2p0 = pk(b2r0, b2r0), b2p1 = pk(b2r1, b2r1);
#pragma unroll
        for (int pp = 0; pp < 6; pp++) {
            V2 r0 = { f2add(c0[2 * pp].a, b2p0), f2add(c0[2 * pp].b, b2p0) };
            V2 r1 = { f2add(c1[2 * pp].a, b2p1), f2add(c1[2 * pp].b, b2p1) };
            r0 = v2max(r0, v2zero());
            r1 = v2max(r1, v2zero());
            if (pp < 5) {
                V2 e1 = { f2add(c0[2 * pp + 1].a, b2p0), f2add(c0[2 * pp + 1].b, b2p0) };
                V2 f1 = { f2add(c1[2 * pp + 1].a, b2p1), f2add(c1[2 * pp + 1].b, b2p1) };
                r0 = v2max(r0, v2max(e1, v2zero()));
                r1 = v2max(r1, v2max(f1, v2zero()));
            }
            pl[pp] = r0;
            ph[pp] = r1;
        }

        // ---- dense 384->10, butterfly, relu, 10->1 ----
        V2 h[10];
#pragma unroll
        for (int o = 0; o < 10; o++) h[o] = v2zero();
#pragma unroll
        for (int pp = 0; pp < 6; pp++) {
#pragma unroll
            for (int half = 0; half < 2; half++) {
                V2 xv = half ? ph[pp] : pl[pp];
                int i = (2 * pp + half) * 32 + lane;
#pragma unroll
                for (int o = 0; o < 10; o++) {
                    float w = d2ws[o * 384 + i];
                    h[o] = v2fma(xv, pk(w, w), h[o]);
                }
            }
        }
#pragma unroll
        for (int off = 16; off > 0; off >>= 1) {
#pragma unroll
            for (int o = 0; o < 10; o++) {
                h[o].a = f2add(h[o].a, __shfl_xor_sync(0xffffffffu, h[o].a, off));
                h[o].b = f2add(h[o].b, __shfl_xor_sync(0xffffffffu, h[o].b, off));
            }
        }
        float sA = d1bias, sB = d1bias, sC = d1bias, sD = d1bias;
#pragma unroll
        for (int o = 0; o < 10; o++) {
            float hA, hB, hC, hD;
            upk(h[o].a, hA, hB); upk(h[o].b, hC, hD);
            float bo = d2bs[o], wo = d1ws[o];
            sA = fmaf(fmaxf(hA + bo, 0.0f), wo, sA);
            sB = fmaf(fmaxf(hB + bo, 0.0f), wo, sB);
            sC = fmaf(fmaxf(hC + bo, 0.0f), wo, sC);
            sD = fmaf(fmaxf(hD + bo, 0.0f), wo, sD);
        }
        float accA = 10.0f * sA - 6.0f;
        float accB = 10.0f * sB - 6.0f;
        float accC = 10.0f * sC - 6.0f;
        float accD = 10.0f * sD - 6.0f;

        // ---- state update + output ----
        if (lane == 0) {
            V2 pv = ld2(&posb[2 * ((head + 24) & 31)]);
            V2 sv = ld2(&spdb[2 * ((head + 24) & 31)]);
            float pA, pB, pC, pD, qA, qB, qC, qD;
            upk(pv.a, pA, pB); upk(pv.b, pC, pD);
            upk(sv.a, qA, qB); upk(sv.b, qC, qD);
            float npA = pA + 0.1f * qA, nsA = qA + 0.1f * accA;
            float npB = pB + 0.1f * qB, nsB = qB + 0.1f * accB;
            float npC = pC + 0.1f * qC, nsC = qC + 0.1f * accC;
            float npD = pD + 0.1f * qD, nsD = qD + 0.1f * accD;
            ((float2*)out)[(size_t)vA * nt + t] = make_float2(npA, nsA);
            if (hasB) ((float2*)out)[(size_t)vB * nt + t] = make_float2(npB, nsB);
            if (hasC) ((float2*)out)[(size_t)vC * nt + t] = make_float2(npC, nsC);
            if (hasD) ((float2*)out)[(size_t)vD * nt + t] = make_float2(npD, nsD);
            st2(&posb[2 * ((head + 25) & 31)], V2{ pk(npA, npB), pk(npC, npD) });
            st2(&spdb[2 * ((head + 25) & 31)], V2{ pk(nsA, nsB), pk(nsC, nsD) });
        }
        head = (head + 1) & 31;
        __syncwarp();
    };

    for (int t = 0; t < nt; t += 2) {
        stepf(t,     lnE0, lnE1);   // even parity
        stepf(t + 1, lnO0, lnO1);   // odd parity
    }
}

extern "C" void kernel_launch(void* const* d_in, const int* in_sizes, int n_in,
                              void* d_out, int out_size) {
    const float* lead = (const float*)d_in[0];
    const float* curs = (const float*)d_in[1];
    // d_in[2] = mask : unused by the reference
    const float* w1  = (const float*)d_in[3];
    const float* b1  = (const float*)d_in[4];
    const float* w2  = (const float*)d_in[5];
    const float* b2  = (const float*)d_in[6];
    const float* d2w = (const float*)d_in[7];
    const float* d2b = (const float*)d_in[8];
    const float* d1w = (const float*)d_in[9];
    const float* d1b = (const float*)d_in[10];

    int nveh = in_sizes[1] / (2 * PAST);
    int lead_len = in_sizes[0] / (nveh * 2);
    int nt = out_size / (nveh * 2);

    cudaFuncSetAttribute(rnncf_kernel, cudaFuncAttributeMaxDynamicSharedMemorySize, SMEM_BYTES);

    int quads = (nveh + 3) / 4;
    int blocks = (quads + WPB - 1) / WPB;
    rnncf_kernel<<<blocks, THREADS, SMEM_BYTES>>>(
        lead, curs, w1, b1, w2, b2, d2w, d2b, d1w, d1b,
        (float*)d_out, nveh, nt, lead_len);
}